// round 1
// baseline (speedup 1.0000x reference)
#include <cuda_runtime.h>
#include <math.h>

// Problem constants (fixed shapes from reference setup_inputs):
// B=4, T=16, T0=12, L=64, C=512, H=8, hd=64, NUM_SEEDS=4
// x:      [4, 768, 512]
// x_ctx:  [4, 16, 64, 512] -> [4096, 512]
// dx_ctx: same
// ctx_mask: [4,16] bool
// weights: qkv_w [1536,512], k_w/v_w/proj_w [512,512], proj_b [512]
// out: [4, 768, 512] float32

// ---------------- scratch (static device globals; no allocations) -----------
__device__ float g_qkv [4 * 768 * 1536];   // [b*768+n][which*512 + h*64 + d]
__device__ float g_kctx[4 * 1024 * 512];   // [b*1024+n][h*64+d]
__device__ float g_vctx[4 * 1024 * 512];
__device__ float g_attn[4 * 768 * 512];    // attention output, pre-proj
__device__ int   g_maskn[64];              // normalized ctx_mask [b*16 + t]

// ---------------- mask normalization (dtype-robust) -------------------------
// ctx_mask may be serialized as 1-byte bool or as int32. Detect: if it is
// int32 (values 0/1, little-endian), every byte at offset i with i%4!=0 in
// the first 64 bytes is zero. For 1-byte bool with random 0/1 data that is
// essentially impossible (p = 2^-48).
__global__ void normalize_mask_kernel(const unsigned char* __restrict__ m8) {
    __shared__ int flag;
    int i = threadIdx.x;          // 0..63
    if (i == 0) flag = 0;
    __syncthreads();
    if ((i & 3) != 0 && m8[i] != 0) atomicOr(&flag, 1);
    __syncthreads();
    int v;
    if (flag) v = (m8[i] != 0) ? 1 : 0;                       // bool layout
    else      v = (((const int*)m8)[i] != 0) ? 1 : 0;         // int32 layout
    g_maskn[i] = v;
}

// ---------------- fp32 NT GEMM: C[m,n] = sum_k A[m,k]*W[n,k] (+bias) --------
// BM=BN=64, BK=16, 256 threads, 4x4 micro-tile. All dims divide exactly.
__global__ __launch_bounds__(256)
void gemm_nt(const float* __restrict__ A, const float* __restrict__ W,
             const float* __restrict__ bias, float* __restrict__ C,
             int M, int N, int K) {
    __shared__ float As[16][68];   // As[kk][row]  (transposed)
    __shared__ float Ws[16][68];   // Ws[kk][col]

    int bm = blockIdx.y * 64;
    int bn = blockIdx.x * 64;
    int tid = threadIdx.x;
    int tx = tid & 15, ty = tid >> 4;
    int lr  = tid >> 2;            // 0..63: row within tile
    int lc4 = (tid & 3) << 2;      // 0,4,8,12: col4 within BK

    const float* Aptr = A + (size_t)(bm + lr) * K + lc4;
    const float* Wptr = W + (size_t)(bn + lr) * K + lc4;

    float acc[4][4] = {};

    for (int k0 = 0; k0 < K; k0 += 16) {
        float4 a4 = *(const float4*)(Aptr + k0);
        float4 w4 = *(const float4*)(Wptr + k0);
        As[lc4 + 0][lr] = a4.x; As[lc4 + 1][lr] = a4.y;
        As[lc4 + 2][lr] = a4.z; As[lc4 + 3][lr] = a4.w;
        Ws[lc4 + 0][lr] = w4.x; Ws[lc4 + 1][lr] = w4.y;
        Ws[lc4 + 2][lr] = w4.z; Ws[lc4 + 3][lr] = w4.w;
        __syncthreads();
#pragma unroll
        for (int kk = 0; kk < 16; kk++) {
            float4 av = *(const float4*)&As[kk][ty * 4];
            float4 wv = *(const float4*)&Ws[kk][tx * 4];
            float a[4] = {av.x, av.y, av.z, av.w};
            float w[4] = {wv.x, wv.y, wv.z, wv.w};
#pragma unroll
            for (int i = 0; i < 4; i++)
#pragma unroll
                for (int j = 0; j < 4; j++)
                    acc[i][j] += a[i] * w[j];
        }
        __syncthreads();
    }

#pragma unroll
    for (int i = 0; i < 4; i++) {
        float bx = bias ? bias[bn + tx * 4 + 0] : 0.f;
        float by = bias ? bias[bn + tx * 4 + 1] : 0.f;
        float bz = bias ? bias[bn + tx * 4 + 2] : 0.f;
        float bw = bias ? bias[bn + tx * 4 + 3] : 0.f;
        float4 r = make_float4(acc[i][0] + bx, acc[i][1] + by,
                               acc[i][2] + bz, acc[i][3] + bw);
        *(float4*)&C[(size_t)(bm + ty * 4 + i) * N + bn + tx * 4] = r;
    }
}

// ---------------- fused flash attention ------------------------------------
// grid = (T0=12, H=8, B=4); block 256 threads.
// One block: 64 queries (frame t0) x up to 17 key chunks of 64 (16 ctx frames
// with frame-granular masking + 1 self frame). Online softmax; masked frames
// skipped entirely (their scores are -inf -> exactly zero weight).
struct AttnSmem {
    float Qs[64][66];   // [d][q], prescaled by hd^-0.5
    float Ks[64][68];   // [d][k]
    float Vs[64][68];   // [k][d]
    float Ps[64][65];   // [k][q]
    float mrow[64];
    float lrow[64];
};

__global__ __launch_bounds__(256)
void attn_kernel(const float* __restrict__ qkv,
                 const float* __restrict__ kctx,
                 const float* __restrict__ vctx,
                 float* __restrict__ outb) {
    extern __shared__ char smem_raw[];
    AttnSmem& sm = *reinterpret_cast<AttnSmem*>(smem_raw);

    int t0 = blockIdx.x, h = blockIdx.y, b = blockIdx.z;
    int tid = threadIdx.x;
    int tx = tid & 15, ty = tid >> 4;
    int lr  = tid >> 2;          // 0..63
    int lc4 = (tid & 3) << 2;    // 0,4,8,12

    // Load Q (which=0), prescale by 1/sqrt(64)=0.125
    const float* qbase = qkv + (size_t)(b * 768 + t0 * 64) * 1536 + h * 64;
#pragma unroll
    for (int c4 = 0; c4 < 64; c4 += 16) {
        int d0 = lc4 + c4;
        float4 v = *(const float4*)(qbase + (size_t)lr * 1536 + d0);
        sm.Qs[d0 + 0][lr] = v.x * 0.125f;
        sm.Qs[d0 + 1][lr] = v.y * 0.125f;
        sm.Qs[d0 + 2][lr] = v.z * 0.125f;
        sm.Qs[d0 + 3][lr] = v.w * 0.125f;
    }
    if (tid < 64) { sm.mrow[tid] = -INFINITY; sm.lrow[tid] = 0.f; }

    float o[4][4];
#pragma unroll
    for (int i = 0; i < 4; i++)
#pragma unroll
        for (int j = 0; j < 4; j++) o[i][j] = 0.f;

    for (int t = 0; t <= 16; t++) {
        const float *kb, *vb;
        int rs;
        if (t < 16) {
            // skip masked-out frames and the non-trivial-mask frame t0+4
            if (!g_maskn[b * 16 + t] || t == t0 + 4) continue;
            kb = kctx + (size_t)(b * 1024 + t * 64) * 512 + h * 64;
            vb = vctx + (size_t)(b * 1024 + t * 64) * 512 + h * 64;
            rs = 512;
        } else {
            // self frame: k at which=1, v at which=2
            kb = qkv + (size_t)(b * 768 + t0 * 64) * 1536 + 512 + h * 64;
            vb = qkv + (size_t)(b * 768 + t0 * 64) * 1536 + 1024 + h * 64;
            rs = 1536;
        }

        __syncthreads();   // protect Ks/Vs/Ps from previous iteration readers
#pragma unroll
        for (int c4 = 0; c4 < 64; c4 += 16) {
            int d0 = lc4 + c4;
            float4 kv = *(const float4*)(kb + (size_t)lr * rs + d0);
            sm.Ks[d0 + 0][lr] = kv.x; sm.Ks[d0 + 1][lr] = kv.y;
            sm.Ks[d0 + 2][lr] = kv.z; sm.Ks[d0 + 3][lr] = kv.w;
            float4 vv = *(const float4*)(vb + (size_t)lr * rs + d0);
            *(float4*)&sm.Vs[lr][d0] = vv;
        }
        __syncthreads();

        // S = Q @ K^T (64x64), 4x4 per thread
        float s[4][4] = {};
#pragma unroll 8
        for (int d = 0; d < 64; d++) {
            float a0 = sm.Qs[d][ty * 4 + 0];
            float a1 = sm.Qs[d][ty * 4 + 1];
            float a2 = sm.Qs[d][ty * 4 + 2];
            float a3 = sm.Qs[d][ty * 4 + 3];
            float4 bv = *(const float4*)&sm.Ks[d][tx * 4];
            s[0][0] += a0 * bv.x; s[0][1] += a0 * bv.y; s[0][2] += a0 * bv.z; s[0][3] += a0 * bv.w;
            s[1][0] += a1 * bv.x; s[1][1] += a1 * bv.y; s[1][2] += a1 * bv.z; s[1][3] += a1 * bv.w;
            s[2][0] += a2 * bv.x; s[2][1] += a2 * bv.y; s[2][2] += a2 * bv.z; s[2][3] += a2 * bv.w;
            s[3][0] += a3 * bv.x; s[3][1] += a3 * bv.y; s[3][2] += a3 * bv.z; s[3][3] += a3 * bv.w;
        }

        // online softmax per query row (each row owned by 16 lanes of a warp half)
#pragma unroll
        for (int i = 0; i < 4; i++) {
            int q = ty * 4 + i;
            float rm = fmaxf(fmaxf(s[i][0], s[i][1]), fmaxf(s[i][2], s[i][3]));
            rm = fmaxf(rm, __shfl_xor_sync(0xffffffffu, rm, 1));
            rm = fmaxf(rm, __shfl_xor_sync(0xffffffffu, rm, 2));
            rm = fmaxf(rm, __shfl_xor_sync(0xffffffffu, rm, 4));
            rm = fmaxf(rm, __shfl_xor_sync(0xffffffffu, rm, 8));
            float mo = sm.mrow[q];
            float mn = fmaxf(mo, rm);
            float rsum = 0.f;
#pragma unroll
            for (int j = 0; j < 4; j++) {
                float p = __expf(s[i][j] - mn);
                s[i][j] = p;
                rsum += p;
            }
            rsum += __shfl_xor_sync(0xffffffffu, rsum, 1);
            rsum += __shfl_xor_sync(0xffffffffu, rsum, 2);
            rsum += __shfl_xor_sync(0xffffffffu, rsum, 4);
            rsum += __shfl_xor_sync(0xffffffffu, rsum, 8);
            float f = expf(mo - mn);   // mo = -inf -> 0 exactly
#pragma unroll
            for (int j = 0; j < 4; j++) o[i][j] *= f;
            if (tx == 0) {
                sm.mrow[q] = mn;
                sm.lrow[q] = sm.lrow[q] * f + rsum;
            }
#pragma unroll
            for (int j = 0; j < 4; j++)
                sm.Ps[tx * 4 + j][q] = s[i][j];
        }
        __syncthreads();

        // O += P @ V
#pragma unroll 8
        for (int k = 0; k < 64; k++) {
            float a0 = sm.Ps[k][ty * 4 + 0];
            float a1 = sm.Ps[k][ty * 4 + 1];
            float a2 = sm.Ps[k][ty * 4 + 2];
            float a3 = sm.Ps[k][ty * 4 + 3];
            float4 bv = *(const float4*)&sm.Vs[k][tx * 4];
            o[0][0] += a0 * bv.x; o[0][1] += a0 * bv.y; o[0][2] += a0 * bv.z; o[0][3] += a0 * bv.w;
            o[1][0] += a1 * bv.x; o[1][1] += a1 * bv.y; o[1][2] += a1 * bv.z; o[1][3] += a1 * bv.w;
            o[2][0] += a2 * bv.x; o[2][1] += a2 * bv.y; o[2][2] += a2 * bv.z; o[2][3] += a2 * bv.w;
            o[3][0] += a3 * bv.x; o[3][1] += a3 * bv.y; o[3][2] += a3 * bv.z; o[3][3] += a3 * bv.w;
        }
    }

    __syncthreads();
#pragma unroll
    for (int i = 0; i < 4; i++) {
        int q = ty * 4 + i;
        float inv = 1.0f / sm.lrow[q];   // self chunk always present -> l > 0
        float4 r = make_float4(o[i][0] * inv, o[i][1] * inv,
                               o[i][2] * inv, o[i][3] * inv);
        *(float4*)&outb[(size_t)(b * 768 + t0 * 64 + q) * 512 + h * 64 + tx * 4] = r;
    }
}

// ---------------- launcher ---------------------------------------------------
extern "C" void kernel_launch(void* const* d_in, const int* in_sizes, int n_in,
                              void* d_out, int out_size) {
    const float* x      = (const float*)d_in[0];
    const float* x_ctx  = (const float*)d_in[1];
    const float* dx_ctx = (const float*)d_in[2];
    const unsigned char* mask = (const unsigned char*)d_in[3];
    const float* qkv_w  = (const float*)d_in[4];
    const float* k_w    = (const float*)d_in[5];
    const float* v_w    = (const float*)d_in[6];
    const float* proj_w = (const float*)d_in[7];
    const float* proj_b = (const float*)d_in[8];
    float* out = (float*)d_out;

    float *p_qkv, *p_kctx, *p_vctx, *p_attn;
    cudaGetSymbolAddress((void**)&p_qkv,  g_qkv);
    cudaGetSymbolAddress((void**)&p_kctx, g_kctx);
    cudaGetSymbolAddress((void**)&p_vctx, g_vctx);
    cudaGetSymbolAddress((void**)&p_attn, g_attn);

    normalize_mask_kernel<<<1, 64>>>(mask);

    // qkv = x @ qkv_w^T : [3072, 1536]
    gemm_nt<<<dim3(1536 / 64, 3072 / 64), 256>>>(x, qkv_w, nullptr, p_qkv, 3072, 1536, 512);
    // k_ctx = dx_ctx @ k_w^T : [4096, 512]
    gemm_nt<<<dim3(512 / 64, 4096 / 64), 256>>>(dx_ctx, k_w, nullptr, p_kctx, 4096, 512, 512);
    // v_ctx = x_ctx @ v_w^T : [4096, 512]
    gemm_nt<<<dim3(512 / 64, 4096 / 64), 256>>>(x_ctx, v_w, nullptr, p_vctx, 4096, 512, 512);

    // fused masked flash attention
    cudaFuncSetAttribute(attn_kernel, cudaFuncAttributeMaxDynamicSharedMemorySize,
                         (int)sizeof(AttnSmem));
    attn_kernel<<<dim3(12, 8, 4), 256, sizeof(AttnSmem)>>>(p_qkv, p_kctx, p_vctx, p_attn);

    // final projection + bias -> d_out
    gemm_nt<<<dim3(512 / 64, 3072 / 64), 256>>>(p_attn, proj_w, proj_b, out, 3072, 512, 512);
}

// round 2
// speedup vs baseline: 1.0043x; 1.0043x over previous
#include <cuda_runtime.h>
#include <math.h>

// Problem constants (fixed shapes from reference setup_inputs):
// B=4, T=16, T0=12, L=64, C=512, H=8, hd=64, NUM_SEEDS=4
// x:      [4, 768, 512]
// x_ctx:  [4, 16, 64, 512] -> [4096, 512]
// dx_ctx: same
// ctx_mask: [4,16] bool
// weights: qkv_w [1536,512], k_w/v_w/proj_w [512,512], proj_b [512]
// out: [4, 768, 512] float32

// ---------------- scratch (static device globals; no allocations) -----------
__device__ float g_qkv [4 * 768 * 1536];   // [b*768+n][which*512 + h*64 + d]
__device__ float g_kctx[4 * 1024 * 512];   // [b*1024+n][h*64+d]
__device__ float g_vctx[4 * 1024 * 512];
__device__ float g_attn[4 * 768 * 512];    // attention output, pre-proj
__device__ int   g_maskn[64];              // normalized ctx_mask [b*16 + t]

// ---------------- mask normalization (dtype-robust) -------------------------
// ctx_mask may be serialized as 1-byte bool or as int32. Detect: if it is
// int32 (values 0/1, little-endian), every byte at offset i with i%4!=0 in
// the first 64 bytes is zero. For 1-byte bool with random 0/1 data that is
// essentially impossible (p = 2^-48).
__global__ void normalize_mask_kernel(const unsigned char* __restrict__ m8) {
    __shared__ int flag;
    int i = threadIdx.x;          // 0..63
    if (i == 0) flag = 0;
    __syncthreads();
    if ((i & 3) != 0 && m8[i] != 0) atomicOr(&flag, 1);
    __syncthreads();
    int v;
    if (flag) v = (m8[i] != 0) ? 1 : 0;                       // bool layout
    else      v = (((const int*)m8)[i] != 0) ? 1 : 0;         // int32 layout
    g_maskn[i] = v;
}

// ---------------- fp32 NT GEMM: C[m,n] = sum_k A[m,k]*W[n,k] (+bias) --------
// BM=BN=64, BK=16, 256 threads, 4x4 micro-tile. All dims divide exactly.
__global__ __launch_bounds__(256)
void gemm_nt(const float* __restrict__ A, const float* __restrict__ W,
             const float* __restrict__ bias, float* __restrict__ C,
             int M, int N, int K) {
    __shared__ float As[16][68];   // As[kk][row]  (transposed)
    __shared__ float Ws[16][68];   // Ws[kk][col]

    int bm = blockIdx.y * 64;
    int bn = blockIdx.x * 64;
    int tid = threadIdx.x;
    int tx = tid & 15, ty = tid >> 4;
    int lr  = tid >> 2;            // 0..63: row within tile
    int lc4 = (tid & 3) << 2;      // 0,4,8,12: col4 within BK

    const float* Aptr = A + (size_t)(bm + lr) * K + lc4;
    const float* Wptr = W + (size_t)(bn + lr) * K + lc4;

    float acc[4][4] = {};

    for (int k0 = 0; k0 < K; k0 += 16) {
        float4 a4 = *(const float4*)(Aptr + k0);
        float4 w4 = *(const float4*)(Wptr + k0);
        As[lc4 + 0][lr] = a4.x; As[lc4 + 1][lr] = a4.y;
        As[lc4 + 2][lr] = a4.z; As[lc4 + 3][lr] = a4.w;
        Ws[lc4 + 0][lr] = w4.x; Ws[lc4 + 1][lr] = w4.y;
        Ws[lc4 + 2][lr] = w4.z; Ws[lc4 + 3][lr] = w4.w;
        __syncthreads();
#pragma unroll
        for (int kk = 0; kk < 16; kk++) {
            float4 av = *(const float4*)&As[kk][ty * 4];
            float4 wv = *(const float4*)&Ws[kk][tx * 4];
            float a[4] = {av.x, av.y, av.z, av.w};
            float w[4] = {wv.x, wv.y, wv.z, wv.w};
#pragma unroll
            for (int i = 0; i < 4; i++)
#pragma unroll
                for (int j = 0; j < 4; j++)
                    acc[i][j] += a[i] * w[j];
        }
        __syncthreads();
    }

#pragma unroll
    for (int i = 0; i < 4; i++) {
        float bx = bias ? bias[bn + tx * 4 + 0] : 0.f;
        float by = bias ? bias[bn + tx * 4 + 1] : 0.f;
        float bz = bias ? bias[bn + tx * 4 + 2] : 0.f;
        float bw = bias ? bias[bn + tx * 4 + 3] : 0.f;
        float4 r = make_float4(acc[i][0] + bx, acc[i][1] + by,
                               acc[i][2] + bz, acc[i][3] + bw);
        *(float4*)&C[(size_t)(bm + ty * 4 + i) * N + bn + tx * 4] = r;
    }
}

// ---------------- fused flash attention ------------------------------------
// grid = (T0=12, H=8, B=4); block 256 threads.
// One block: 64 queries (frame t0) x up to 17 key chunks of 64 (16 ctx frames
// with frame-granular masking + 1 self frame). Online softmax; masked frames
// skipped entirely (their scores are -inf -> exactly zero weight).
struct AttnSmem {
    float Qs[64][66];   // [d][q], prescaled by hd^-0.5
    float Ks[64][68];   // [d][k]
    float Vs[64][68];   // [k][d]
    float Ps[64][65];   // [k][q]
    float mrow[64];
    float lrow[64];
};

__global__ __launch_bounds__(256)
void attn_kernel(const float* __restrict__ qkv,
                 const float* __restrict__ kctx,
                 const float* __restrict__ vctx,
                 float* __restrict__ outb) {
    extern __shared__ char smem_raw[];
    AttnSmem& sm = *reinterpret_cast<AttnSmem*>(smem_raw);

    int t0 = blockIdx.x, h = blockIdx.y, b = blockIdx.z;
    int tid = threadIdx.x;
    int tx = tid & 15, ty = tid >> 4;
    int lr  = tid >> 2;          // 0..63
    int lc4 = (tid & 3) << 2;    // 0,4,8,12

    // Load Q (which=0), prescale by 1/sqrt(64)=0.125
    const float* qbase = qkv + (size_t)(b * 768 + t0 * 64) * 1536 + h * 64;
#pragma unroll
    for (int c4 = 0; c4 < 64; c4 += 16) {
        int d0 = lc4 + c4;
        float4 v = *(const float4*)(qbase + (size_t)lr * 1536 + d0);
        sm.Qs[d0 + 0][lr] = v.x * 0.125f;
        sm.Qs[d0 + 1][lr] = v.y * 0.125f;
        sm.Qs[d0 + 2][lr] = v.z * 0.125f;
        sm.Qs[d0 + 3][lr] = v.w * 0.125f;
    }
    if (tid < 64) { sm.mrow[tid] = -INFINITY; sm.lrow[tid] = 0.f; }

    float o[4][4];
#pragma unroll
    for (int i = 0; i < 4; i++)
#pragma unroll
        for (int j = 0; j < 4; j++) o[i][j] = 0.f;

    for (int t = 0; t <= 16; t++) {
        const float *kb, *vb;
        int rs;
        if (t < 16) {
            // skip masked-out frames and the non-trivial-mask frame t0+4
            if (!g_maskn[b * 16 + t] || t == t0 + 4) continue;
            kb = kctx + (size_t)(b * 1024 + t * 64) * 512 + h * 64;
            vb = vctx + (size_t)(b * 1024 + t * 64) * 512 + h * 64;
            rs = 512;
        } else {
            // self frame: k at which=1, v at which=2
            kb = qkv + (size_t)(b * 768 + t0 * 64) * 1536 + 512 + h * 64;
            vb = qkv + (size_t)(b * 768 + t0 * 64) * 1536 + 1024 + h * 64;
            rs = 1536;
        }

        __syncthreads();   // protect Ks/Vs/Ps from previous iteration readers
#pragma unroll
        for (int c4 = 0; c4 < 64; c4 += 16) {
            int d0 = lc4 + c4;
            float4 kv = *(const float4*)(kb + (size_t)lr * rs + d0);
            sm.Ks[d0 + 0][lr] = kv.x; sm.Ks[d0 + 1][lr] = kv.y;
            sm.Ks[d0 + 2][lr] = kv.z; sm.Ks[d0 + 3][lr] = kv.w;
            float4 vv = *(const float4*)(vb + (size_t)lr * rs + d0);
            *(float4*)&sm.Vs[lr][d0] = vv;
        }
        __syncthreads();

        // S = Q @ K^T (64x64), 4x4 per thread
        float s[4][4] = {};
#pragma unroll 8
        for (int d = 0; d < 64; d++) {
            float a0 = sm.Qs[d][ty * 4 + 0];
            float a1 = sm.Qs[d][ty * 4 + 1];
            float a2 = sm.Qs[d][ty * 4 + 2];
            float a3 = sm.Qs[d][ty * 4 + 3];
            float4 bv = *(const float4*)&sm.Ks[d][tx * 4];
            s[0][0] += a0 * bv.x; s[0][1] += a0 * bv.y; s[0][2] += a0 * bv.z; s[0][3] += a0 * bv.w;
            s[1][0] += a1 * bv.x; s[1][1] += a1 * bv.y; s[1][2] += a1 * bv.z; s[1][3] += a1 * bv.w;
            s[2][0] += a2 * bv.x; s[2][1] += a2 * bv.y; s[2][2] += a2 * bv.z; s[2][3] += a2 * bv.w;
            s[3][0] += a3 * bv.x; s[3][1] += a3 * bv.y; s[3][2] += a3 * bv.z; s[3][3] += a3 * bv.w;
        }

        // online softmax per query row (each row owned by 16 lanes of a warp half)
#pragma unroll
        for (int i = 0; i < 4; i++) {
            int q = ty * 4 + i;
            float rm = fmaxf(fmaxf(s[i][0], s[i][1]), fmaxf(s[i][2], s[i][3]));
            rm = fmaxf(rm, __shfl_xor_sync(0xffffffffu, rm, 1));
            rm = fmaxf(rm, __shfl_xor_sync(0xffffffffu, rm, 2));
            rm = fmaxf(rm, __shfl_xor_sync(0xffffffffu, rm, 4));
            rm = fmaxf(rm, __shfl_xor_sync(0xffffffffu, rm, 8));
            float mo = sm.mrow[q];
            float mn = fmaxf(mo, rm);
            float rsum = 0.f;
#pragma unroll
            for (int j = 0; j < 4; j++) {
                float p = __expf(s[i][j] - mn);
                s[i][j] = p;
                rsum += p;
            }
            rsum += __shfl_xor_sync(0xffffffffu, rsum, 1);
            rsum += __shfl_xor_sync(0xffffffffu, rsum, 2);
            rsum += __shfl_xor_sync(0xffffffffu, rsum, 4);
            rsum += __shfl_xor_sync(0xffffffffu, rsum, 8);
            float f = expf(mo - mn);   // mo = -inf -> 0 exactly
#pragma unroll
            for (int j = 0; j < 4; j++) o[i][j] *= f;
            if (tx == 0) {
                sm.mrow[q] = mn;
                sm.lrow[q] = sm.lrow[q] * f + rsum;
            }
#pragma unroll
            for (int j = 0; j < 4; j++)
                sm.Ps[tx * 4 + j][q] = s[i][j];
        }
        __syncthreads();

        // O += P @ V
#pragma unroll 8
        for (int k = 0; k < 64; k++) {
            float a0 = sm.Ps[k][ty * 4 + 0];
            float a1 = sm.Ps[k][ty * 4 + 1];
            float a2 = sm.Ps[k][ty * 4 + 2];
            float a3 = sm.Ps[k][ty * 4 + 3];
            float4 bv = *(const float4*)&sm.Vs[k][tx * 4];
            o[0][0] += a0 * bv.x; o[0][1] += a0 * bv.y; o[0][2] += a0 * bv.z; o[0][3] += a0 * bv.w;
            o[1][0] += a1 * bv.x; o[1][1] += a1 * bv.y; o[1][2] += a1 * bv.z; o[1][3] += a1 * bv.w;
            o[2][0] += a2 * bv.x; o[2][1] += a2 * bv.y; o[2][2] += a2 * bv.z; o[2][3] += a2 * bv.w;
            o[3][0] += a3 * bv.x; o[3][1] += a3 * bv.y; o[3][2] += a3 * bv.z; o[3][3] += a3 * bv.w;
        }
    }

    __syncthreads();
#pragma unroll
    for (int i = 0; i < 4; i++) {
        int q = ty * 4 + i;
        float inv = 1.0f / sm.lrow[q];   // self chunk always present -> l > 0
        float4 r = make_float4(o[i][0] * inv, o[i][1] * inv,
                               o[i][2] * inv, o[i][3] * inv);
        *(float4*)&outb[(size_t)(b * 768 + t0 * 64 + q) * 512 + h * 64 + tx * 4] = r;
    }
}

// ---------------- launcher ---------------------------------------------------
extern "C" void kernel_launch(void* const* d_in, const int* in_sizes, int n_in,
                              void* d_out, int out_size) {
    const float* x      = (const float*)d_in[0];
    const float* x_ctx  = (const float*)d_in[1];
    const float* dx_ctx = (const float*)d_in[2];
    const unsigned char* mask = (const unsigned char*)d_in[3];
    const float* qkv_w  = (const float*)d_in[4];
    const float* k_w    = (const float*)d_in[5];
    const float* v_w    = (const float*)d_in[6];
    const float* proj_w = (const float*)d_in[7];
    const float* proj_b = (const float*)d_in[8];
    float* out = (float*)d_out;

    float *p_qkv, *p_kctx, *p_vctx, *p_attn;
    cudaGetSymbolAddress((void**)&p_qkv,  g_qkv);
    cudaGetSymbolAddress((void**)&p_kctx, g_kctx);
    cudaGetSymbolAddress((void**)&p_vctx, g_vctx);
    cudaGetSymbolAddress((void**)&p_attn, g_attn);

    normalize_mask_kernel<<<1, 64>>>(mask);

    // qkv = x @ qkv_w^T : [3072, 1536]
    gemm_nt<<<dim3(1536 / 64, 3072 / 64), 256>>>(x, qkv_w, nullptr, p_qkv, 3072, 1536, 512);
    // k_ctx = dx_ctx @ k_w^T : [4096, 512]
    gemm_nt<<<dim3(512 / 64, 4096 / 64), 256>>>(dx_ctx, k_w, nullptr, p_kctx, 4096, 512, 512);
    // v_ctx = x_ctx @ v_w^T : [4096, 512]
    gemm_nt<<<dim3(512 / 64, 4096 / 64), 256>>>(x_ctx, v_w, nullptr, p_vctx, 4096, 512, 512);

    // fused masked flash attention
    cudaFuncSetAttribute(attn_kernel, cudaFuncAttributeMaxDynamicSharedMemorySize,
                         (int)sizeof(AttnSmem));
    attn_kernel<<<dim3(12, 8, 4), 256, sizeof(AttnSmem)>>>(p_qkv, p_kctx, p_vctx, p_attn);

    // final projection + bias -> d_out
    gemm_nt<<<dim3(512 / 64, 3072 / 64), 256>>>(p_attn, proj_w, proj_b, out, 3072, 512, 512);
}

// round 3
// speedup vs baseline: 1.1969x; 1.1918x over previous
#include <cuda_runtime.h>
#include <math.h>

// Problem constants (fixed shapes from reference setup_inputs):
// B=4, T=16, T0=12, L=64, C=512, H=8, hd=64, NUM_SEEDS=4

// ---------------- scratch (static device globals; no allocations) -----------
__device__ float g_qkv [4 * 768 * 1536];   // [b*768+n][which*512 + h*64 + d]
__device__ float g_kctx[4 * 1024 * 512];   // [b*1024+n][h*64+d]
__device__ float g_vctx[4 * 1024 * 512];
__device__ float g_attn[4 * 768 * 512];    // attention output, pre-proj
__device__ int   g_maskn[64];              // normalized ctx_mask [b*16 + t]

// ---------------- mask normalization (dtype-robust) -------------------------
__global__ void normalize_mask_kernel(const unsigned char* __restrict__ m8) {
    __shared__ int flag;
    int i = threadIdx.x;          // 0..63
    if (i == 0) flag = 0;
    __syncthreads();
    if ((i & 3) != 0 && m8[i] != 0) atomicOr(&flag, 1);
    __syncthreads();
    int v;
    if (flag) v = (m8[i] != 0) ? 1 : 0;                       // bool layout
    else      v = (((const int*)m8)[i] != 0) ? 1 : 0;         // int32 layout
    g_maskn[i] = v;
}

// ---------------- fp32 NT GEMM: C[m,n] = sum_k A[m,k]*W[n,k] (+bias) --------
// Templated tile: BM x BN, micro-tile TM x TN, BK=16, 256 threads,
// double-buffered smem with register-staged global prefetch.
template<int BM, int BN, int TM, int TN>
__global__ __launch_bounds__(256, 2)
void gemm_nt_t(const float* __restrict__ A, const float* __restrict__ W,
               const float* __restrict__ bias, float* __restrict__ C,
               int M, int N, int K) {
    constexpr int BK = 16;
    constexpr int PAD = 4;
    __shared__ float As[2][BK][BM + PAD];   // [buf][k][row]  (A transposed)
    __shared__ float Ws[2][BK][BN + PAD];   // [buf][k][col]

    constexpr int TX = BN / TN;                 // threads along N
    constexpr int nA = (BM * BK / 4) / 256;     // float4 per thread (A tile)
    constexpr int nB = (BN * BK / 4) / 256;
    static_assert((BM / TM) * (BN / TN) == 256, "256 threads");
    static_assert(nA >= 1 && nB >= 1, "load split");

    const int tid = threadIdx.x;
    const int tx = tid % TX;
    const int ty = tid / TX;
    const int bm = blockIdx.y * BM;
    const int bn = blockIdx.x * BN;

    int arow[nA], ac4[nA], wrow[nB], wc4[nB];
#pragma unroll
    for (int i = 0; i < nA; i++) { int f = tid + i * 256; arow[i] = f >> 2; ac4[i] = (f & 3) << 2; }
#pragma unroll
    for (int i = 0; i < nB; i++) { int f = tid + i * 256; wrow[i] = f >> 2; wc4[i] = (f & 3) << 2; }

    const float* Abase = A + (size_t)bm * K;
    const float* Wbase = W + (size_t)bn * K;

    float4 aReg[nA], wReg[nB];
#pragma unroll
    for (int i = 0; i < nA; i++)
        aReg[i] = *(const float4*)(Abase + (size_t)arow[i] * K + ac4[i]);
#pragma unroll
    for (int i = 0; i < nB; i++)
        wReg[i] = *(const float4*)(Wbase + (size_t)wrow[i] * K + wc4[i]);

#pragma unroll
    for (int i = 0; i < nA; i++) {
        As[0][ac4[i] + 0][arow[i]] = aReg[i].x;
        As[0][ac4[i] + 1][arow[i]] = aReg[i].y;
        As[0][ac4[i] + 2][arow[i]] = aReg[i].z;
        As[0][ac4[i] + 3][arow[i]] = aReg[i].w;
    }
#pragma unroll
    for (int i = 0; i < nB; i++) {
        Ws[0][wc4[i] + 0][wrow[i]] = wReg[i].x;
        Ws[0][wc4[i] + 1][wrow[i]] = wReg[i].y;
        Ws[0][wc4[i] + 2][wrow[i]] = wReg[i].z;
        Ws[0][wc4[i] + 3][wrow[i]] = wReg[i].w;
    }

    float acc[TM][TN] = {};
    int cur = 0;

    for (int k0 = 0; k0 < K; k0 += BK) {
        __syncthreads();
        const bool more = (k0 + BK) < K;
        if (more) {
            const int kn = k0 + BK;
#pragma unroll
            for (int i = 0; i < nA; i++)
                aReg[i] = *(const float4*)(Abase + (size_t)arow[i] * K + kn + ac4[i]);
#pragma unroll
            for (int i = 0; i < nB; i++)
                wReg[i] = *(const float4*)(Wbase + (size_t)wrow[i] * K + kn + wc4[i]);
        }

#pragma unroll
        for (int kk = 0; kk < BK; kk++) {
            float a[TM], w[TN];
#pragma unroll
            for (int i = 0; i < TM; i += 4)
                *(float4*)&a[i] = *(const float4*)&As[cur][kk][ty * TM + i];
#pragma unroll
            for (int j = 0; j < TN; j += 4)
                *(float4*)&w[j] = *(const float4*)&Ws[cur][kk][tx * TN + j];
#pragma unroll
            for (int i = 0; i < TM; i++)
#pragma unroll
                for (int j = 0; j < TN; j++)
                    acc[i][j] += a[i] * w[j];
        }

        if (more) {
            const int nxt = cur ^ 1;
#pragma unroll
            for (int i = 0; i < nA; i++) {
                As[nxt][ac4[i] + 0][arow[i]] = aReg[i].x;
                As[nxt][ac4[i] + 1][arow[i]] = aReg[i].y;
                As[nxt][ac4[i] + 2][arow[i]] = aReg[i].z;
                As[nxt][ac4[i] + 3][arow[i]] = aReg[i].w;
            }
#pragma unroll
            for (int i = 0; i < nB; i++) {
                Ws[nxt][wc4[i] + 0][wrow[i]] = wReg[i].x;
                Ws[nxt][wc4[i] + 1][wrow[i]] = wReg[i].y;
                Ws[nxt][wc4[i] + 2][wrow[i]] = wReg[i].z;
                Ws[nxt][wc4[i] + 3][wrow[i]] = wReg[i].w;
            }
        }
        cur ^= 1;
    }

#pragma unroll
    for (int i = 0; i < TM; i++) {
        const int row = bm + ty * TM + i;
#pragma unroll
        for (int j = 0; j < TN; j += 4) {
            const int col = bn + tx * TN + j;
            float4 r;
            if (bias) {
                r.x = acc[i][j + 0] + bias[col + 0];
                r.y = acc[i][j + 1] + bias[col + 1];
                r.z = acc[i][j + 2] + bias[col + 2];
                r.w = acc[i][j + 3] + bias[col + 3];
            } else {
                r.x = acc[i][j + 0]; r.y = acc[i][j + 1];
                r.z = acc[i][j + 2]; r.w = acc[i][j + 3];
            }
            *(float4*)&C[(size_t)row * N + col] = r;
        }
    }
}

// ---------------- fused flash attention ------------------------------------
// grid = (T0=12, H=8, B=4); block 256 threads. 64 queries x up to 17 key
// chunks of 64. Online softmax; masked frames skipped entirely.
struct AttnSmem {
    float Qs[64][66];   // [d][q], prescaled by hd^-0.5
    float Ks[64][68];   // [d][k]
    float Vs[64][68];   // [k][d]
    float Ps[64][65];   // [k][q]
    float mrow[64];
    float lrow[64];
};

__global__ __launch_bounds__(256)
void attn_kernel(const float* __restrict__ qkv,
                 const float* __restrict__ kctx,
                 const float* __restrict__ vctx,
                 float* __restrict__ outb) {
    extern __shared__ char smem_raw[];
    AttnSmem& sm = *reinterpret_cast<AttnSmem*>(smem_raw);

    int t0 = blockIdx.x, h = blockIdx.y, b = blockIdx.z;
    int tid = threadIdx.x;
    int tx = tid & 15, ty = tid >> 4;
    int lr  = tid >> 2;          // 0..63
    int lc4 = (tid & 3) << 2;    // 0,4,8,12

    const float* qbase = qkv + (size_t)(b * 768 + t0 * 64) * 1536 + h * 64;
#pragma unroll
    for (int c4 = 0; c4 < 64; c4 += 16) {
        int d0 = lc4 + c4;
        float4 v = *(const float4*)(qbase + (size_t)lr * 1536 + d0);
        sm.Qs[d0 + 0][lr] = v.x * 0.125f;
        sm.Qs[d0 + 1][lr] = v.y * 0.125f;
        sm.Qs[d0 + 2][lr] = v.z * 0.125f;
        sm.Qs[d0 + 3][lr] = v.w * 0.125f;
    }
    if (tid < 64) { sm.mrow[tid] = -INFINITY; sm.lrow[tid] = 0.f; }

    float o[4][4];
#pragma unroll
    for (int i = 0; i < 4; i++)
#pragma unroll
        for (int j = 0; j < 4; j++) o[i][j] = 0.f;

    for (int t = 0; t <= 16; t++) {
        const float *kb, *vb;
        int rs;
        if (t < 16) {
            if (!g_maskn[b * 16 + t] || t == t0 + 4) continue;
            kb = kctx + (size_t)(b * 1024 + t * 64) * 512 + h * 64;
            vb = vctx + (size_t)(b * 1024 + t * 64) * 512 + h * 64;
            rs = 512;
        } else {
            kb = qkv + (size_t)(b * 768 + t0 * 64) * 1536 + 512 + h * 64;
            vb = qkv + (size_t)(b * 768 + t0 * 64) * 1536 + 1024 + h * 64;
            rs = 1536;
        }

        __syncthreads();
#pragma unroll
        for (int c4 = 0; c4 < 64; c4 += 16) {
            int d0 = lc4 + c4;
            float4 kv = *(const float4*)(kb + (size_t)lr * rs + d0);
            sm.Ks[d0 + 0][lr] = kv.x; sm.Ks[d0 + 1][lr] = kv.y;
            sm.Ks[d0 + 2][lr] = kv.z; sm.Ks[d0 + 3][lr] = kv.w;
            float4 vv = *(const float4*)(vb + (size_t)lr * rs + d0);
            *(float4*)&sm.Vs[lr][d0] = vv;
        }
        __syncthreads();

        float s[4][4] = {};
#pragma unroll 8
        for (int d = 0; d < 64; d++) {
            float a0 = sm.Qs[d][ty * 4 + 0];
            float a1 = sm.Qs[d][ty * 4 + 1];
            float a2 = sm.Qs[d][ty * 4 + 2];
            float a3 = sm.Qs[d][ty * 4 + 3];
            float4 bv = *(const float4*)&sm.Ks[d][tx * 4];
            s[0][0] += a0 * bv.x; s[0][1] += a0 * bv.y; s[0][2] += a0 * bv.z; s[0][3] += a0 * bv.w;
            s[1][0] += a1 * bv.x; s[1][1] += a1 * bv.y; s[1][2] += a1 * bv.z; s[1][3] += a1 * bv.w;
            s[2][0] += a2 * bv.x; s[2][1] += a2 * bv.y; s[2][2] += a2 * bv.z; s[2][3] += a2 * bv.w;
            s[3][0] += a3 * bv.x; s[3][1] += a3 * bv.y; s[3][2] += a3 * bv.z; s[3][3] += a3 * bv.w;
        }

#pragma unroll
        for (int i = 0; i < 4; i++) {
            int q = ty * 4 + i;
            float rm = fmaxf(fmaxf(s[i][0], s[i][1]), fmaxf(s[i][2], s[i][3]));
            rm = fmaxf(rm, __shfl_xor_sync(0xffffffffu, rm, 1));
            rm = fmaxf(rm, __shfl_xor_sync(0xffffffffu, rm, 2));
            rm = fmaxf(rm, __shfl_xor_sync(0xffffffffu, rm, 4));
            rm = fmaxf(rm, __shfl_xor_sync(0xffffffffu, rm, 8));
            float mo = sm.mrow[q];
            float mn = fmaxf(mo, rm);
            float rsum = 0.f;
#pragma unroll
            for (int j = 0; j < 4; j++) {
                float p = __expf(s[i][j] - mn);
                s[i][j] = p;
                rsum += p;
            }
            rsum += __shfl_xor_sync(0xffffffffu, rsum, 1);
            rsum += __shfl_xor_sync(0xffffffffu, rsum, 2);
            rsum += __shfl_xor_sync(0xffffffffu, rsum, 4);
            rsum += __shfl_xor_sync(0xffffffffu, rsum, 8);
            float f = expf(mo - mn);   // mo = -inf -> 0 exactly
#pragma unroll
            for (int j = 0; j < 4; j++) o[i][j] *= f;
            if (tx == 0) {
                sm.mrow[q] = mn;
                sm.lrow[q] = sm.lrow[q] * f + rsum;
            }
#pragma unroll
            for (int j = 0; j < 4; j++)
                sm.Ps[tx * 4 + j][q] = s[i][j];
        }
        __syncthreads();

#pragma unroll 8
        for (int k = 0; k < 64; k++) {
            float a0 = sm.Ps[k][ty * 4 + 0];
            float a1 = sm.Ps[k][ty * 4 + 1];
            float a2 = sm.Ps[k][ty * 4 + 2];
            float a3 = sm.Ps[k][ty * 4 + 3];
            float4 bv = *(const float4*)&sm.Vs[k][tx * 4];
            o[0][0] += a0 * bv.x; o[0][1] += a0 * bv.y; o[0][2] += a0 * bv.z; o[0][3] += a0 * bv.w;
            o[1][0] += a1 * bv.x; o[1][1] += a1 * bv.y; o[1][2] += a1 * bv.z; o[1][3] += a1 * bv.w;
            o[2][0] += a2 * bv.x; o[2][1] += a2 * bv.y; o[2][2] += a2 * bv.z; o[2][3] += a2 * bv.w;
            o[3][0] += a3 * bv.x; o[3][1] += a3 * bv.y; o[3][2] += a3 * bv.z; o[3][3] += a3 * bv.w;
        }
    }

    __syncthreads();
#pragma unroll
    for (int i = 0; i < 4; i++) {
        int q = ty * 4 + i;
        float inv = 1.0f / sm.lrow[q];
        float4 r = make_float4(o[i][0] * inv, o[i][1] * inv,
                               o[i][2] * inv, o[i][3] * inv);
        *(float4*)&outb[(size_t)(b * 768 + t0 * 64 + q) * 512 + h * 64 + tx * 4] = r;
    }
}

// ---------------- launcher ---------------------------------------------------
extern "C" void kernel_launch(void* const* d_in, const int* in_sizes, int n_in,
                              void* d_out, int out_size) {
    const float* x      = (const float*)d_in[0];
    const float* x_ctx  = (const float*)d_in[1];
    const float* dx_ctx = (const float*)d_in[2];
    const unsigned char* mask = (const unsigned char*)d_in[3];
    const float* qkv_w  = (const float*)d_in[4];
    const float* k_w    = (const float*)d_in[5];
    const float* v_w    = (const float*)d_in[6];
    const float* proj_w = (const float*)d_in[7];
    const float* proj_b = (const float*)d_in[8];
    float* out = (float*)d_out;

    float *p_qkv, *p_kctx, *p_vctx, *p_attn;
    cudaGetSymbolAddress((void**)&p_qkv,  g_qkv);
    cudaGetSymbolAddress((void**)&p_kctx, g_kctx);
    cudaGetSymbolAddress((void**)&p_vctx, g_vctx);
    cudaGetSymbolAddress((void**)&p_attn, g_attn);

    normalize_mask_kernel<<<1, 64>>>(mask);

    // qkv = x @ qkv_w^T : [3072, 1536]
    gemm_nt_t<128, 128, 8, 8><<<dim3(1536 / 128, 3072 / 128), 256>>>(
        x, qkv_w, nullptr, p_qkv, 3072, 1536, 512);
    // k_ctx = dx_ctx @ k_w^T : [4096, 512]
    gemm_nt_t<128, 64, 8, 4><<<dim3(512 / 64, 4096 / 128), 256>>>(
        dx_ctx, k_w, nullptr, p_kctx, 4096, 512, 512);
    // v_ctx = x_ctx @ v_w^T : [4096, 512]
    gemm_nt_t<128, 64, 8, 4><<<dim3(512 / 64, 4096 / 128), 256>>>(
        x_ctx, v_w, nullptr, p_vctx, 4096, 512, 512);

    // fused masked flash attention
    cudaFuncSetAttribute(attn_kernel, cudaFuncAttributeMaxDynamicSharedMemorySize,
                         (int)sizeof(AttnSmem));
    attn_kernel<<<dim3(12, 8, 4), 256, sizeof(AttnSmem)>>>(p_qkv, p_kctx, p_vctx, p_attn);

    // final projection + bias -> d_out
    gemm_nt_t<128, 64, 8, 4><<<dim3(512 / 64, 3072 / 128), 256>>>(
        p_attn, proj_w, proj_b, out, 3072, 512, 512);
}

// round 5
// speedup vs baseline: 1.6433x; 1.3730x over previous
#include <cuda_runtime.h>
#include <cuda_bf16.h>
#include <math.h>
#include <stdint.h>

// Problem constants: B=4, T=16, T0=12, L=64, C=512, H=8, hd=64, NUM_SEEDS=4

// ---------------- scratch (static device globals; no allocations) -----------
__device__ float g_qkv [4 * 768 * 1536];   // [b*768+n][which*512 + h*64 + d]
__device__ float g_kctx[4 * 1024 * 512];   // [b*1024+n][h*64+d]
__device__ float g_vctx[4 * 1024 * 512];
__device__ float g_attn[4 * 768 * 512];    // attention output, pre-proj (fp32)
__device__ int   g_maskn[64];              // normalized ctx_mask [b*16 + t]

// split (hi/lo bf16) operands for tensor-core GEMMs
__device__ __align__(16) __nv_bfloat16 g_xh [3072 * 512], g_xl [3072 * 512];
__device__ __align__(16) __nv_bfloat16 g_xch[4096 * 512], g_xcl[4096 * 512];
__device__ __align__(16) __nv_bfloat16 g_dxh[4096 * 512], g_dxl[4096 * 512];
__device__ __align__(16) __nv_bfloat16 g_qwh[1536 * 512], g_qwl[1536 * 512];
__device__ __align__(16) __nv_bfloat16 g_kwh[ 512 * 512], g_kwl[ 512 * 512];
__device__ __align__(16) __nv_bfloat16 g_vwh[ 512 * 512], g_vwl[ 512 * 512];
__device__ __align__(16) __nv_bfloat16 g_pwh[ 512 * 512], g_pwl[ 512 * 512];
__device__ __align__(16) __nv_bfloat16 g_ah [3072 * 512], g_al [3072 * 512];

// ---------------- helpers ----------------------------------------------------
__device__ __forceinline__ uint32_t s2u(const void* p) {
    uint32_t a;
    asm("{ .reg .u64 t; cvta.to.shared.u64 t, %1; cvt.u32.u64 %0, t; }"
        : "=r"(a) : "l"(p));
    return a;
}
__device__ __forceinline__ uint32_t lds32(uint32_t a) {
    uint32_t v;
    asm volatile("ld.shared.b32 %0, [%1];" : "=r"(v) : "r"(a));
    return v;
}
__device__ __forceinline__ void cp16(uint32_t dst, const void* src) {
    asm volatile("cp.async.cg.shared.global [%0], [%1], 16;"
                 :: "r"(dst), "l"(src));
}
__device__ __forceinline__ void mma_bf16(float* c, const uint32_t* a, const uint32_t* b) {
    asm volatile(
        "mma.sync.aligned.m16n8k16.row.col.f32.bf16.bf16.f32 "
        "{%0,%1,%2,%3}, {%4,%5,%6,%7}, {%8,%9}, {%0,%1,%2,%3};"
        : "+f"(c[0]), "+f"(c[1]), "+f"(c[2]), "+f"(c[3])
        : "r"(a[0]), "r"(a[1]), "r"(a[2]), "r"(a[3]), "r"(b[0]), "r"(b[1]));
}
__device__ __forceinline__ uint32_t pack_bf(__nv_bfloat16 a, __nv_bfloat16 b) {
    return (uint32_t)__bfloat16_as_ushort(a) | ((uint32_t)__bfloat16_as_ushort(b) << 16);
}

// ---------------- split fp32 -> hi/lo bf16 -----------------------------------
__global__ void split_kernel(const float4* __restrict__ src,
                             uint2* __restrict__ hi, uint2* __restrict__ lo, int n4) {
    int i = blockIdx.x * 256 + threadIdx.x;
    if (i >= n4) return;
    float4 v = src[i];
    __nv_bfloat16 h0 = __float2bfloat16(v.x), h1 = __float2bfloat16(v.y);
    __nv_bfloat16 h2 = __float2bfloat16(v.z), h3 = __float2bfloat16(v.w);
    __nv_bfloat16 l0 = __float2bfloat16(v.x - __bfloat162float(h0));
    __nv_bfloat16 l1 = __float2bfloat16(v.y - __bfloat162float(h1));
    __nv_bfloat16 l2 = __float2bfloat16(v.z - __bfloat162float(h2));
    __nv_bfloat16 l3 = __float2bfloat16(v.w - __bfloat162float(h3));
    hi[i] = make_uint2(pack_bf(h0, h1), pack_bf(h2, h3));
    lo[i] = make_uint2(pack_bf(l0, l1), pack_bf(l2, l3));
}

// ---------------- mask normalization (dtype-robust) --------------------------
__global__ void normalize_mask_kernel(const unsigned char* __restrict__ m8) {
    __shared__ int flag;
    int i = threadIdx.x;          // 0..63
    if (i == 0) flag = 0;
    __syncthreads();
    if ((i & 3) != 0 && m8[i] != 0) atomicOr(&flag, 1);
    __syncthreads();
    int v;
    if (flag) v = (m8[i] != 0) ? 1 : 0;                       // bool layout
    else      v = (((const int*)m8)[i] != 0) ? 1 : 0;         // int32 layout
    g_maskn[i] = v;
}

// ---------------- tensor-core split-bf16 GEMM: C = A @ W^T (+bias) ----------
// A,W given pre-split as hi/lo bf16 [.,K] row-major; C fp32 [M,N].
// Block 128x64, BK=32, 256 threads = 8 warps (4 m x 2 n), warp tile 32x32.
// 3-term emulation: Ah*Bh + Ah*Bl + Al*Bh accumulated in fp32.
#define PITCHB 80            // smem row pitch bytes (40 bf16)
#define A_BYTES (128 * PITCHB)      // 10240
#define B_BYTES (64 * PITCHB)       // 5120
#define BUF_BYTES (2 * A_BYTES + 2 * B_BYTES)   // 30720
#define GEMM_SMEM (2 * BUF_BYTES)               // 61440

__global__ __launch_bounds__(256, 2)
void gemm_tc(const __nv_bfloat16* __restrict__ Ah, const __nv_bfloat16* __restrict__ Al,
             const __nv_bfloat16* __restrict__ Wh, const __nv_bfloat16* __restrict__ Wl,
             const float* __restrict__ bias, float* __restrict__ C,
             int M, int N, int K) {
    extern __shared__ char smem[];
    const uint32_t sb = s2u(smem);
    const int tid = threadIdx.x;
    const int wid = tid >> 5, lane = tid & 31;
    const int gid = lane >> 2, tig = lane & 3;
    const int bm = blockIdx.y * 128, bn = blockIdx.x * 64;
    const int wm = wid & 3, wn = wid >> 2;          // warp tile: m=wm*32, n=wn*32

    const int arow = tid >> 2;          // A load: f=tid(+256): row=f>>2, seg=f&3
    const int aseg = tid & 3;

    float acc[2][4][4];
#pragma unroll
    for (int mf = 0; mf < 2; mf++)
#pragma unroll
        for (int nf = 0; nf < 4; nf++)
#pragma unroll
            for (int r = 0; r < 4; r++) acc[mf][nf][r] = 0.f;

    const int nc = K >> 5;   // chunks of 32

    // cp.async issue for chunk c into buffer buf
    auto issue = [&](int c, int buf) {
        uint32_t base = sb + buf * BUF_BYTES;
        const int kofs = c * 32 + aseg * 8;
#pragma unroll
        for (int i = 0; i < 2; i++) {
            int row = arow + i * 64;
            uint32_t d = base + row * PITCHB + aseg * 16;
            cp16(d,            Ah + (size_t)(bm + row) * K + kofs);
            cp16(d + A_BYTES,  Al + (size_t)(bm + row) * K + kofs);
        }
        {
            int row = arow;  // 0..63
            uint32_t d = base + 2 * A_BYTES + row * PITCHB + aseg * 16;
            cp16(d,            Wh + (size_t)(bn + row) * K + kofs);
            cp16(d + B_BYTES,  Wl + (size_t)(bn + row) * K + kofs);
        }
        asm volatile("cp.async.commit_group;");
    };

    issue(0, 0);

    for (int c = 0; c < nc; c++) {
        const int buf = c & 1;
        if (c + 1 < nc) {
            issue(c + 1, buf ^ 1);
            asm volatile("cp.async.wait_group 1;");
        } else {
            asm volatile("cp.async.wait_group 0;");
        }
        __syncthreads();

        const uint32_t abase = sb + buf * BUF_BYTES;
        const uint32_t bbase = abase + 2 * A_BYTES;

#pragma unroll
        for (int kf = 0; kf < 2; kf++) {
            uint32_t ah[2][4], al[2][4], bh[4][2], bl[4][2];
            const uint32_t kbyt = (tig * 2 + kf * 16) * 2;
#pragma unroll
            for (int mf = 0; mf < 2; mf++) {
                uint32_t ad = abase + (wm * 32 + mf * 16 + gid) * PITCHB + kbyt;
                ah[mf][0] = lds32(ad);
                ah[mf][1] = lds32(ad + 8 * PITCHB);
                ah[mf][2] = lds32(ad + 16);
                ah[mf][3] = lds32(ad + 8 * PITCHB + 16);
                al[mf][0] = lds32(ad + A_BYTES);
                al[mf][1] = lds32(ad + A_BYTES + 8 * PITCHB);
                al[mf][2] = lds32(ad + A_BYTES + 16);
                al[mf][3] = lds32(ad + A_BYTES + 8 * PITCHB + 16);
            }
#pragma unroll
            for (int nf = 0; nf < 4; nf++) {
                uint32_t bd = bbase + (wn * 32 + nf * 8 + gid) * PITCHB + kbyt;
                bh[nf][0] = lds32(bd);
                bh[nf][1] = lds32(bd + 16);
                bl[nf][0] = lds32(bd + B_BYTES);
                bl[nf][1] = lds32(bd + B_BYTES + 16);
            }
#pragma unroll
            for (int mf = 0; mf < 2; mf++)
#pragma unroll
                for (int nf = 0; nf < 4; nf++) {
                    mma_bf16(acc[mf][nf], ah[mf], bh[nf]);
                    mma_bf16(acc[mf][nf], ah[mf], bl[nf]);
                    mma_bf16(acc[mf][nf], al[mf], bh[nf]);
                }
        }
        __syncthreads();
    }

    // epilogue
#pragma unroll
    for (int mf = 0; mf < 2; mf++) {
#pragma unroll
        for (int nf = 0; nf < 4; nf++) {
            int row = bm + wm * 32 + mf * 16 + gid;
            int col = bn + wn * 32 + nf * 8 + tig * 2;
            float b0 = bias ? bias[col] : 0.f;
            float b1 = bias ? bias[col + 1] : 0.f;
            float2 v0 = make_float2(acc[mf][nf][0] + b0, acc[mf][nf][1] + b1);
            float2 v1 = make_float2(acc[mf][nf][2] + b0, acc[mf][nf][3] + b1);
            *(float2*)&C[(size_t)row * N + col] = v0;
            *(float2*)&C[(size_t)(row + 8) * N + col] = v1;
        }
    }
}

// ---------------- fused flash attention (fp32) -------------------------------
// grid = (T0=12, H=8, B=4); block 256 threads. Writes fp32 out + hi/lo splits.
struct AttnSmem {
    float Qs[64][66];   // [d][q], prescaled by hd^-0.5
    float Ks[64][68];   // [d][k]
    float Vs[64][68];   // [k][d]
    float Ps[64][65];   // [k][q]
    float mrow[64];
    float lrow[64];
};

__global__ __launch_bounds__(256)
void attn_kernel(const float* __restrict__ qkv,
                 const float* __restrict__ kctx,
                 const float* __restrict__ vctx,
                 float* __restrict__ outb,
                 __nv_bfloat16* __restrict__ outh,
                 __nv_bfloat16* __restrict__ outl) {
    extern __shared__ char smem_raw[];
    AttnSmem& sm = *reinterpret_cast<AttnSmem*>(smem_raw);

    int t0 = blockIdx.x, h = blockIdx.y, b = blockIdx.z;
    int tid = threadIdx.x;
    int tx = tid & 15, ty = tid >> 4;
    int lr  = tid >> 2;          // 0..63
    int lc4 = (tid & 3) << 2;    // 0,4,8,12

    const float* qbase = qkv + (size_t)(b * 768 + t0 * 64) * 1536 + h * 64;
#pragma unroll
    for (int c4 = 0; c4 < 64; c4 += 16) {
        int d0 = lc4 + c4;
        float4 v = *(const float4*)(qbase + (size_t)lr * 1536 + d0);
        sm.Qs[d0 + 0][lr] = v.x * 0.125f;
        sm.Qs[d0 + 1][lr] = v.y * 0.125f;
        sm.Qs[d0 + 2][lr] = v.z * 0.125f;
        sm.Qs[d0 + 3][lr] = v.w * 0.125f;
    }
    if (tid < 64) { sm.mrow[tid] = -INFINITY; sm.lrow[tid] = 0.f; }

    float o[4][4];
#pragma unroll
    for (int i = 0; i < 4; i++)
#pragma unroll
        for (int j = 0; j < 4; j++) o[i][j] = 0.f;

    for (int t = 0; t <= 16; t++) {
        const float *kb, *vb;
        int rs;
        if (t < 16) {
            if (!g_maskn[b * 16 + t] || t == t0 + 4) continue;
            kb = kctx + (size_t)(b * 1024 + t * 64) * 512 + h * 64;
            vb = vctx + (size_t)(b * 1024 + t * 64) * 512 + h * 64;
            rs = 512;
        } else {
            kb = qkv + (size_t)(b * 768 + t0 * 64) * 1536 + 512 + h * 64;
            vb = qkv + (size_t)(b * 768 + t0 * 64) * 1536 + 1024 + h * 64;
            rs = 1536;
        }

        __syncthreads();
#pragma unroll
        for (int c4 = 0; c4 < 64; c4 += 16) {
            int d0 = lc4 + c4;
            float4 kv = *(const float4*)(kb + (size_t)lr * rs + d0);
            sm.Ks[d0 + 0][lr] = kv.x; sm.Ks[d0 + 1][lr] = kv.y;
            sm.Ks[d0 + 2][lr] = kv.z; sm.Ks[d0 + 3][lr] = kv.w;
            float4 vv = *(const float4*)(vb + (size_t)lr * rs + d0);
            *(float4*)&sm.Vs[lr][d0] = vv;
        }
        __syncthreads();

        float s[4][4] = {};
#pragma unroll 8
        for (int d = 0; d < 64; d++) {
            float a0 = sm.Qs[d][ty * 4 + 0];
            float a1 = sm.Qs[d][ty * 4 + 1];
            float a2 = sm.Qs[d][ty * 4 + 2];
            float a3 = sm.Qs[d][ty * 4 + 3];
            float4 bv = *(const float4*)&sm.Ks[d][tx * 4];
            s[0][0] += a0 * bv.x; s[0][1] += a0 * bv.y; s[0][2] += a0 * bv.z; s[0][3] += a0 * bv.w;
            s[1][0] += a1 * bv.x; s[1][1] += a1 * bv.y; s[1][2] += a1 * bv.z; s[1][3] += a1 * bv.w;
            s[2][0] += a2 * bv.x; s[2][1] += a2 * bv.y; s[2][2] += a2 * bv.z; s[2][3] += a2 * bv.w;
            s[3][0] += a3 * bv.x; s[3][1] += a3 * bv.y; s[3][2] += a3 * bv.z; s[3][3] += a3 * bv.w;
        }

#pragma unroll
        for (int i = 0; i < 4; i++) {
            int q = ty * 4 + i;
            float rm = fmaxf(fmaxf(s[i][0], s[i][1]), fmaxf(s[i][2], s[i][3]));
            rm = fmaxf(rm, __shfl_xor_sync(0xffffffffu, rm, 1));
            rm = fmaxf(rm, __shfl_xor_sync(0xffffffffu, rm, 2));
            rm = fmaxf(rm, __shfl_xor_sync(0xffffffffu, rm, 4));
            rm = fmaxf(rm, __shfl_xor_sync(0xffffffffu, rm, 8));
            float mo = sm.mrow[q];
            float mn = fmaxf(mo, rm);
            float rsum = 0.f;
#pragma unroll
            for (int j = 0; j < 4; j++) {
                float p = __expf(s[i][j] - mn);
                s[i][j] = p;
                rsum += p;
            }
            rsum += __shfl_xor_sync(0xffffffffu, rsum, 1);
            rsum += __shfl_xor_sync(0xffffffffu, rsum, 2);
            rsum += __shfl_xor_sync(0xffffffffu, rsum, 4);
            rsum += __shfl_xor_sync(0xffffffffu, rsum, 8);
            float f = expf(mo - mn);   // mo = -inf -> 0 exactly
#pragma unroll
            for (int j = 0; j < 4; j++) o[i][j] *= f;
            if (tx == 0) {
                sm.mrow[q] = mn;
                sm.lrow[q] = sm.lrow[q] * f + rsum;
            }
#pragma unroll
            for (int j = 0; j < 4; j++)
                sm.Ps[tx * 4 + j][q] = s[i][j];
        }
        __syncthreads();

#pragma unroll 8
        for (int k = 0; k < 64; k++) {
            float a0 = sm.Ps[k][ty * 4 + 0];
            float a1 = sm.Ps[k][ty * 4 + 1];
            float a2 = sm.Ps[k][ty * 4 + 2];
            float a3 = sm.Ps[k][ty * 4 + 3];
            float4 bv = *(const float4*)&sm.Vs[k][tx * 4];
            o[0][0] += a0 * bv.x; o[0][1] += a0 * bv.y; o[0][2] += a0 * bv.z; o[0][3] += a0 * bv.w;
            o[1][0] += a1 * bv.x; o[1][1] += a1 * bv.y; o[1][2] += a1 * bv.z; o[1][3] += a1 * bv.w;
            o[2][0] += a2 * bv.x; o[2][1] += a2 * bv.y; o[2][2] += a2 * bv.z; o[2][3] += a2 * bv.w;
            o[3][0] += a3 * bv.x; o[3][1] += a3 * bv.y; o[3][2] += a3 * bv.z; o[3][3] += a3 * bv.w;
        }
    }

    __syncthreads();
#pragma unroll
    for (int i = 0; i < 4; i++) {
        int q = ty * 4 + i;
        float inv = 1.0f / sm.lrow[q];
        float4 r = make_float4(o[i][0] * inv, o[i][1] * inv,
                               o[i][2] * inv, o[i][3] * inv);
        size_t idx = (size_t)(b * 768 + t0 * 64 + q) * 512 + h * 64 + tx * 4;
        *(float4*)&outb[idx] = r;
        // split to hi/lo bf16 for the proj GEMM
        __nv_bfloat16 h0 = __float2bfloat16(r.x), h1 = __float2bfloat16(r.y);
        __nv_bfloat16 h2 = __float2bfloat16(r.z), h3 = __float2bfloat16(r.w);
        __nv_bfloat16 l0 = __float2bfloat16(r.x - __bfloat162float(h0));
        __nv_bfloat16 l1 = __float2bfloat16(r.y - __bfloat162float(h1));
        __nv_bfloat16 l2 = __float2bfloat16(r.z - __bfloat162float(h2));
        __nv_bfloat16 l3 = __float2bfloat16(r.w - __bfloat162float(h3));
        *(uint2*)&outh[idx] = make_uint2(pack_bf(h0, h1), pack_bf(h2, h3));
        *(uint2*)&outl[idx] = make_uint2(pack_bf(l0, l1), pack_bf(l2, l3));
    }
}

// ---------------- launcher ---------------------------------------------------
extern "C" void kernel_launch(void* const* d_in, const int* in_sizes, int n_in,
                              void* d_out, int out_size) {
    const float* x      = (const float*)d_in[0];
    const float* x_ctx  = (const float*)d_in[1];
    const float* dx_ctx = (const float*)d_in[2];
    const unsigned char* mask = (const unsigned char*)d_in[3];
    const float* qkv_w  = (const float*)d_in[4];
    const float* k_w    = (const float*)d_in[5];
    const float* v_w    = (const float*)d_in[6];
    const float* proj_w = (const float*)d_in[7];
    const float* proj_b = (const float*)d_in[8];
    float* out = (float*)d_out;

    float *p_qkv, *p_kctx, *p_vctx, *p_attn;
    cudaGetSymbolAddress((void**)&p_qkv,  g_qkv);
    cudaGetSymbolAddress((void**)&p_kctx, g_kctx);
    cudaGetSymbolAddress((void**)&p_vctx, g_vctx);
    cudaGetSymbolAddress((void**)&p_attn, g_attn);

    __nv_bfloat16 *xh, *xl, *xch, *xcl, *dxh, *dxl, *qwh, *qwl,
                  *kwh, *kwl, *vwh, *vwl, *pwh, *pwl, *ah, *al;
    cudaGetSymbolAddress((void**)&xh,  g_xh);  cudaGetSymbolAddress((void**)&xl,  g_xl);
    cudaGetSymbolAddress((void**)&xch, g_xch); cudaGetSymbolAddress((void**)&xcl, g_xcl);
    cudaGetSymbolAddress((void**)&dxh, g_dxh); cudaGetSymbolAddress((void**)&dxl, g_dxl);
    cudaGetSymbolAddress((void**)&qwh, g_qwh); cudaGetSymbolAddress((void**)&qwl, g_qwl);
    cudaGetSymbolAddress((void**)&kwh, g_kwh); cudaGetSymbolAddress((void**)&kwl, g_kwl);
    cudaGetSymbolAddress((void**)&vwh, g_vwh); cudaGetSymbolAddress((void**)&vwl, g_vwl);
    cudaGetSymbolAddress((void**)&pwh, g_pwh); cudaGetSymbolAddress((void**)&pwl, g_pwl);
    cudaGetSymbolAddress((void**)&ah,  g_ah);  cudaGetSymbolAddress((void**)&al,  g_al);

    cudaFuncSetAttribute(gemm_tc, cudaFuncAttributeMaxDynamicSharedMemorySize, GEMM_SMEM);
    cudaFuncSetAttribute(attn_kernel, cudaFuncAttributeMaxDynamicSharedMemorySize,
                         (int)sizeof(AttnSmem));

    normalize_mask_kernel<<<1, 64>>>(mask);

    // presplit all GEMM operands into hi/lo bf16
    auto split = [](const float* s, __nv_bfloat16* h, __nv_bfloat16* l, int n) {
        int n4 = n / 4;
        split_kernel<<<(n4 + 255) / 256, 256>>>((const float4*)s, (uint2*)h, (uint2*)l, n4);
    };
    split(x,      xh,  xl,  3072 * 512);
    split(x_ctx,  xch, xcl, 4096 * 512);
    split(dx_ctx, dxh, dxl, 4096 * 512);
    split(qkv_w,  qwh, qwl, 1536 * 512);
    split(k_w,    kwh, kwl,  512 * 512);
    split(v_w,    vwh, vwl,  512 * 512);
    split(proj_w, pwh, pwl,  512 * 512);

    // qkv = x @ qkv_w^T : [3072, 1536]
    gemm_tc<<<dim3(1536 / 64, 3072 / 128), 256, GEMM_SMEM>>>(
        xh, xl, qwh, qwl, nullptr, p_qkv, 3072, 1536, 512);
    // k_ctx = dx_ctx @ k_w^T : [4096, 512]
    gemm_tc<<<dim3(512 / 64, 4096 / 128), 256, GEMM_SMEM>>>(
        dxh, dxl, kwh, kwl, nullptr, p_kctx, 4096, 512, 512);
    // v_ctx = x_ctx @ v_w^T : [4096, 512]
    gemm_tc<<<dim3(512 / 64, 4096 / 128), 256, GEMM_SMEM>>>(
        xch, xcl, vwh, vwl, nullptr, p_vctx, 4096, 512, 512);

    // fused masked flash attention (writes fp32 + hi/lo splits)
    attn_kernel<<<dim3(12, 8, 4), 256, sizeof(AttnSmem)>>>(
        p_qkv, p_kctx, p_vctx, p_attn, ah, al);

    // final projection + bias -> d_out
    gemm_tc<<<dim3(512 / 64, 3072 / 128), 256, GEMM_SMEM>>>(
        ah, al, pwh, pwl, proj_b, out, 3072, 512, 512);
}

// round 6
// speedup vs baseline: 1.7838x; 1.0855x over previous
#include <cuda_runtime.h>
#include <cuda_bf16.h>
#include <math.h>
#include <stdint.h>

// Problem constants: B=4, T=16, T0=12, L=64, C=512, H=8, hd=64, NUM_SEEDS=4

// ---------------- scratch (static device globals; no allocations) -----------
__device__ float g_qkv [4 * 768 * 1536];   // [b*768+n][which*512 + h*64 + d]
__device__ float g_kctx[4 * 1024 * 512];   // [b*1024+n][h*64+d]
__device__ float g_vctx[4 * 1024 * 512];
__device__ int   g_maskn[64];              // normalized ctx_mask [b*16 + t]

// split (hi/lo bf16) operands for tensor-core GEMMs
__device__ __align__(16) __nv_bfloat16 g_xh [3072 * 512], g_xl [3072 * 512];
__device__ __align__(16) __nv_bfloat16 g_xch[4096 * 512], g_xcl[4096 * 512];
__device__ __align__(16) __nv_bfloat16 g_dxh[4096 * 512], g_dxl[4096 * 512];
__device__ __align__(16) __nv_bfloat16 g_qwh[1536 * 512], g_qwl[1536 * 512];
__device__ __align__(16) __nv_bfloat16 g_kwh[ 512 * 512], g_kwl[ 512 * 512];
__device__ __align__(16) __nv_bfloat16 g_vwh[ 512 * 512], g_vwl[ 512 * 512];
__device__ __align__(16) __nv_bfloat16 g_pwh[ 512 * 512], g_pwl[ 512 * 512];
__device__ __align__(16) __nv_bfloat16 g_ah [3072 * 512], g_al [3072 * 512];

// ---------------- helpers ----------------------------------------------------
__device__ __forceinline__ uint32_t s2u(const void* p) {
    uint32_t a;
    asm("{ .reg .u64 t; cvta.to.shared.u64 t, %1; cvt.u32.u64 %0, t; }"
        : "=r"(a) : "l"(p));
    return a;
}
__device__ __forceinline__ void cp16(uint32_t dst, const void* src) {
    asm volatile("cp.async.cg.shared.global [%0], [%1], 16;"
                 :: "r"(dst), "l"(src));
}
__device__ __forceinline__ void ldm_x4(uint32_t* r, uint32_t addr) {
    asm volatile("ldmatrix.sync.aligned.m8n8.x4.shared.b16 {%0,%1,%2,%3}, [%4];"
                 : "=r"(r[0]), "=r"(r[1]), "=r"(r[2]), "=r"(r[3]) : "r"(addr));
}
__device__ __forceinline__ void mma_bf16(float* c, const uint32_t* a, const uint32_t* b) {
    asm volatile(
        "mma.sync.aligned.m16n8k16.row.col.f32.bf16.bf16.f32 "
        "{%0,%1,%2,%3}, {%4,%5,%6,%7}, {%8,%9}, {%0,%1,%2,%3};"
        : "+f"(c[0]), "+f"(c[1]), "+f"(c[2]), "+f"(c[3])
        : "r"(a[0]), "r"(a[1]), "r"(a[2]), "r"(a[3]), "r"(b[0]), "r"(b[1]));
}
__device__ __forceinline__ uint32_t pack_bf(__nv_bfloat16 a, __nv_bfloat16 b) {
    return (uint32_t)__bfloat16_as_ushort(a) | ((uint32_t)__bfloat16_as_ushort(b) << 16);
}

// ---------------- fused split: fp32 -> hi/lo bf16, all arrays, one launch ----
struct SplitArgs {
    const float4* src[7];
    uint2* hi[7];
    uint2* lo[7];
    int n4[7];
};
__global__ __launch_bounds__(256)
void split_all(SplitArgs a) {
    const int arr = blockIdx.y;
    const int n4 = a.n4[arr];
    const float4* __restrict__ s = a.src[arr];
    uint2* __restrict__ hp = a.hi[arr];
    uint2* __restrict__ lp = a.lo[arr];
    const int step = gridDim.x * 256;
    for (int i = blockIdx.x * 256 + threadIdx.x; i < n4; i += step) {
        float4 v = s[i];
        __nv_bfloat16 h0 = __float2bfloat16(v.x), h1 = __float2bfloat16(v.y);
        __nv_bfloat16 h2 = __float2bfloat16(v.z), h3 = __float2bfloat16(v.w);
        __nv_bfloat16 l0 = __float2bfloat16(v.x - __bfloat162float(h0));
        __nv_bfloat16 l1 = __float2bfloat16(v.y - __bfloat162float(h1));
        __nv_bfloat16 l2 = __float2bfloat16(v.z - __bfloat162float(h2));
        __nv_bfloat16 l3 = __float2bfloat16(v.w - __bfloat162float(h3));
        hp[i] = make_uint2(pack_bf(h0, h1), pack_bf(h2, h3));
        lp[i] = make_uint2(pack_bf(l0, l1), pack_bf(l2, l3));
    }
}

// ---------------- mask normalization (dtype-robust) --------------------------
__global__ void normalize_mask_kernel(const unsigned char* __restrict__ m8) {
    __shared__ int flag;
    int i = threadIdx.x;          // 0..63
    if (i == 0) flag = 0;
    __syncthreads();
    if ((i & 3) != 0 && m8[i] != 0) atomicOr(&flag, 1);
    __syncthreads();
    int v;
    if (flag) v = (m8[i] != 0) ? 1 : 0;                       // bool layout
    else      v = (((const int*)m8)[i] != 0) ? 1 : 0;         // int32 layout
    g_maskn[i] = v;
}

// ---------------- tensor-core split-bf16 GEMM: C = A @ W^T (+bias) ----------
// A,W pre-split hi/lo bf16 [.,K] row-major; C fp32 [M,N].
// Block 128x64, BK=32, 8 warps (4m x 2n), warp tile 32x32, ldmatrix fragments.
// 3-term emulation: Ah*Bh + Ah*Bl + Al*Bh accumulated in fp32.
#define PITCHB 80                         // smem row pitch bytes (32 bf16 + pad)
#define A_BYTES (128 * PITCHB)            // 10240
#define B_BYTES (64 * PITCHB)             // 5120
#define BUF_BYTES (2 * A_BYTES + 2 * B_BYTES)   // 30720
#define GEMM_SMEM (2 * BUF_BYTES)               // 61440

__global__ __launch_bounds__(256, 2)
void gemm_tc(const __nv_bfloat16* __restrict__ Ah, const __nv_bfloat16* __restrict__ Al,
             const __nv_bfloat16* __restrict__ Wh, const __nv_bfloat16* __restrict__ Wl,
             const float* __restrict__ bias, float* __restrict__ C,
             int M, int N, int K) {
    extern __shared__ char smem[];
    const uint32_t sb = s2u(smem);
    const int tid = threadIdx.x;
    const int wid = tid >> 5, lane = tid & 31;
    const int gid = lane >> 2, tig = lane & 3;
    const int bm = blockIdx.y * 128, bn = blockIdx.x * 64;
    const int wm = wid & 3, wn = wid >> 2;          // warp tile m=wm*32, n=wn*32

    const int arow = tid >> 2;
    const int aseg = tid & 3;

    float acc[2][4][4];
#pragma unroll
    for (int mf = 0; mf < 2; mf++)
#pragma unroll
        for (int nf = 0; nf < 4; nf++)
#pragma unroll
            for (int r = 0; r < 4; r++) acc[mf][nf][r] = 0.f;

    const int nc = K >> 5;

    auto issue = [&](int c, int buf) {
        uint32_t base = sb + buf * BUF_BYTES;
        const int kofs = c * 32 + aseg * 8;
#pragma unroll
        for (int i = 0; i < 2; i++) {
            int row = arow + i * 64;
            uint32_t d = base + row * PITCHB + aseg * 16;
            cp16(d,            Ah + (size_t)(bm + row) * K + kofs);
            cp16(d + A_BYTES,  Al + (size_t)(bm + row) * K + kofs);
        }
        {
            int row = arow;
            uint32_t d = base + 2 * A_BYTES + row * PITCHB + aseg * 16;
            cp16(d,            Wh + (size_t)(bn + row) * K + kofs);
            cp16(d + B_BYTES,  Wl + (size_t)(bn + row) * K + kofs);
        }
        asm volatile("cp.async.commit_group;");
    };

    issue(0, 0);

    // per-lane ldmatrix address components
    const uint32_t a_row16 = lane & 15;            // row within 16
    const uint32_t a_cofs  = (lane >> 4) * 16;     // col-half byte offset
    const uint32_t b_nrow  = (lane & 7) + ((lane >> 4) & 1) * 8;  // n within 16
    const uint32_t b_kofs  = ((lane >> 3) & 1) * 16;              // k-half bytes

    for (int c = 0; c < nc; c++) {
        const int buf = c & 1;
        if (c + 1 < nc) {
            issue(c + 1, buf ^ 1);
            asm volatile("cp.async.wait_group 1;");
        } else {
            asm volatile("cp.async.wait_group 0;");
        }
        __syncthreads();

        const uint32_t abase = sb + buf * BUF_BYTES;
        const uint32_t bbase = abase + 2 * A_BYTES;

#pragma unroll
        for (int kf = 0; kf < 2; kf++) {
            uint32_t ah[2][4], al[2][4], bh[4][2], bl[4][2];
            const uint32_t kb = kf * 32;   // 16 bf16 = 32 bytes per k-half
#pragma unroll
            for (int mf = 0; mf < 2; mf++) {
                uint32_t ad = abase + (wm * 32 + mf * 16 + a_row16) * PITCHB
                            + a_cofs + kb;
                ldm_x4(ah[mf], ad);
                ldm_x4(al[mf], ad + A_BYTES);
            }
#pragma unroll
            for (int pr = 0; pr < 2; pr++) {   // n pairs (16 rows each)
                uint32_t bd = bbase + (wn * 32 + pr * 16 + b_nrow) * PITCHB
                            + b_kofs + kb;
                uint32_t th[4], tl[4];
                ldm_x4(th, bd);
                ldm_x4(tl, bd + B_BYTES);
                bh[pr * 2 + 0][0] = th[0]; bh[pr * 2 + 0][1] = th[1];
                bh[pr * 2 + 1][0] = th[2]; bh[pr * 2 + 1][1] = th[3];
                bl[pr * 2 + 0][0] = tl[0]; bl[pr * 2 + 0][1] = tl[1];
                bl[pr * 2 + 1][0] = tl[2]; bl[pr * 2 + 1][1] = tl[3];
            }
#pragma unroll
            for (int mf = 0; mf < 2; mf++)
#pragma unroll
                for (int nf = 0; nf < 4; nf++) {
                    mma_bf16(acc[mf][nf], ah[mf], bh[nf]);
                    mma_bf16(acc[mf][nf], ah[mf], bl[nf]);
                    mma_bf16(acc[mf][nf], al[mf], bh[nf]);
                }
        }
        __syncthreads();
    }

#pragma unroll
    for (int mf = 0; mf < 2; mf++) {
#pragma unroll
        for (int nf = 0; nf < 4; nf++) {
            int row = bm + wm * 32 + mf * 16 + gid;
            int col = bn + wn * 32 + nf * 8 + tig * 2;
            float b0 = bias ? bias[col] : 0.f;
            float b1 = bias ? bias[col + 1] : 0.f;
            float2 v0 = make_float2(acc[mf][nf][0] + b0, acc[mf][nf][1] + b1);
            float2 v1 = make_float2(acc[mf][nf][2] + b0, acc[mf][nf][3] + b1);
            *(float2*)&C[(size_t)row * N + col] = v0;
            *(float2*)&C[(size_t)(row + 8) * N + col] = v1;
        }
    }
}

// ---------------- fused flash attention (fp32) -------------------------------
// grid = (T0=12, H=8, B=4); block 256. Writes hi/lo bf16 splits only.
struct AttnSmem {
    float Qs[64][66];   // [d][q], prescaled by hd^-0.5
    float Ks[64][68];   // [d][k]
    float Vs[64][68];   // [k][d]
    float Ps[64][65];   // [k][q]
    float mrow[64];
    float lrow[64];
};

__global__ __launch_bounds__(256)
void attn_kernel(const float* __restrict__ qkv,
                 const float* __restrict__ kctx,
                 const float* __restrict__ vctx,
                 __nv_bfloat16* __restrict__ outh,
                 __nv_bfloat16* __restrict__ outl) {
    extern __shared__ char smem_raw[];
    AttnSmem& sm = *reinterpret_cast<AttnSmem*>(smem_raw);

    int t0 = blockIdx.x, h = blockIdx.y, b = blockIdx.z;
    int tid = threadIdx.x;
    int tx = tid & 15, ty = tid >> 4;
    int lr  = tid >> 2;          // 0..63
    int lc4 = (tid & 3) << 2;    // 0,4,8,12

    const float* qbase = qkv + (size_t)(b * 768 + t0 * 64) * 1536 + h * 64;
#pragma unroll
    for (int c4 = 0; c4 < 64; c4 += 16) {
        int d0 = lc4 + c4;
        float4 v = *(const float4*)(qbase + (size_t)lr * 1536 + d0);
        sm.Qs[d0 + 0][lr] = v.x * 0.125f;
        sm.Qs[d0 + 1][lr] = v.y * 0.125f;
        sm.Qs[d0 + 2][lr] = v.z * 0.125f;
        sm.Qs[d0 + 3][lr] = v.w * 0.125f;
    }
    if (tid < 64) { sm.mrow[tid] = -INFINITY; sm.lrow[tid] = 0.f; }

    float o[4][4];
#pragma unroll
    for (int i = 0; i < 4; i++)
#pragma unroll
        for (int j = 0; j < 4; j++) o[i][j] = 0.f;

    for (int t = 0; t <= 16; t++) {
        const float *kb, *vb;
        int rs;
        if (t < 16) {
            if (!g_maskn[b * 16 + t] || t == t0 + 4) continue;
            kb = kctx + (size_t)(b * 1024 + t * 64) * 512 + h * 64;
            vb = vctx + (size_t)(b * 1024 + t * 64) * 512 + h * 64;
            rs = 512;
        } else {
            kb = qkv + (size_t)(b * 768 + t0 * 64) * 1536 + 512 + h * 64;
            vb = qkv + (size_t)(b * 768 + t0 * 64) * 1536 + 1024 + h * 64;
            rs = 1536;
        }

        __syncthreads();
#pragma unroll
        for (int c4 = 0; c4 < 64; c4 += 16) {
            int d0 = lc4 + c4;
            float4 kv = *(const float4*)(kb + (size_t)lr * rs + d0);
            sm.Ks[d0 + 0][lr] = kv.x; sm.Ks[d0 + 1][lr] = kv.y;
            sm.Ks[d0 + 2][lr] = kv.z; sm.Ks[d0 + 3][lr] = kv.w;
            float4 vv = *(const float4*)(vb + (size_t)lr * rs + d0);
            *(float4*)&sm.Vs[lr][d0] = vv;
        }
        __syncthreads();

        float s[4][4] = {};
#pragma unroll 8
        for (int d = 0; d < 64; d++) {
            float a0 = sm.Qs[d][ty * 4 + 0];
            float a1 = sm.Qs[d][ty * 4 + 1];
            float a2 = sm.Qs[d][ty * 4 + 2];
            float a3 = sm.Qs[d][ty * 4 + 3];
            float4 bv = *(const float4*)&sm.Ks[d][tx * 4];
            s[0][0] += a0 * bv.x; s[0][1] += a0 * bv.y; s[0][2] += a0 * bv.z; s[0][3] += a0 * bv.w;
            s[1][0] += a1 * bv.x; s[1][1] += a1 * bv.y; s[1][2] += a1 * bv.z; s[1][3] += a1 * bv.w;
            s[2][0] += a2 * bv.x; s[2][1] += a2 * bv.y; s[2][2] += a2 * bv.z; s[2][3] += a2 * bv.w;
            s[3][0] += a3 * bv.x; s[3][1] += a3 * bv.y; s[3][2] += a3 * bv.z; s[3][3] += a3 * bv.w;
        }

#pragma unroll
        for (int i = 0; i < 4; i++) {
            int q = ty * 4 + i;
            float rm = fmaxf(fmaxf(s[i][0], s[i][1]), fmaxf(s[i][2], s[i][3]));
            rm = fmaxf(rm, __shfl_xor_sync(0xffffffffu, rm, 1));
            rm = fmaxf(rm, __shfl_xor_sync(0xffffffffu, rm, 2));
            rm = fmaxf(rm, __shfl_xor_sync(0xffffffffu, rm, 4));
            rm = fmaxf(rm, __shfl_xor_sync(0xffffffffu, rm, 8));
            float mo = sm.mrow[q];
            float mn = fmaxf(mo, rm);
            float rsum = 0.f;
#pragma unroll
            for (int j = 0; j < 4; j++) {
                float p = __expf(s[i][j] - mn);
                s[i][j] = p;
                rsum += p;
            }
            rsum += __shfl_xor_sync(0xffffffffu, rsum, 1);
            rsum += __shfl_xor_sync(0xffffffffu, rsum, 2);
            rsum += __shfl_xor_sync(0xffffffffu, rsum, 4);
            rsum += __shfl_xor_sync(0xffffffffu, rsum, 8);
            float f = expf(mo - mn);   // mo = -inf -> 0 exactly
#pragma unroll
            for (int j = 0; j < 4; j++) o[i][j] *= f;
            if (tx == 0) {
                sm.mrow[q] = mn;
                sm.lrow[q] = sm.lrow[q] * f + rsum;
            }
#pragma unroll
            for (int j = 0; j < 4; j++)
                sm.Ps[tx * 4 + j][q] = s[i][j];
        }
        __syncthreads();

#pragma unroll 8
        for (int k = 0; k < 64; k++) {
            float a0 = sm.Ps[k][ty * 4 + 0];
            float a1 = sm.Ps[k][ty * 4 + 1];
            float a2 = sm.Ps[k][ty * 4 + 2];
            float a3 = sm.Ps[k][ty * 4 + 3];
            float4 bv = *(const float4*)&sm.Vs[k][tx * 4];
            o[0][0] += a0 * bv.x; o[0][1] += a0 * bv.y; o[0][2] += a0 * bv.z; o[0][3] += a0 * bv.w;
            o[1][0] += a1 * bv.x; o[1][1] += a1 * bv.y; o[1][2] += a1 * bv.z; o[1][3] += a1 * bv.w;
            o[2][0] += a2 * bv.x; o[2][1] += a2 * bv.y; o[2][2] += a2 * bv.z; o[2][3] += a2 * bv.w;
            o[3][0] += a3 * bv.x; o[3][1] += a3 * bv.y; o[3][2] += a3 * bv.z; o[3][3] += a3 * bv.w;
        }
    }

    __syncthreads();
#pragma unroll
    for (int i = 0; i < 4; i++) {
        int q = ty * 4 + i;
        float inv = 1.0f / sm.lrow[q];
        float4 r = make_float4(o[i][0] * inv, o[i][1] * inv,
                               o[i][2] * inv, o[i][3] * inv);
        size_t idx = (size_t)(b * 768 + t0 * 64 + q) * 512 + h * 64 + tx * 4;
        __nv_bfloat16 h0 = __float2bfloat16(r.x), h1 = __float2bfloat16(r.y);
        __nv_bfloat16 h2 = __float2bfloat16(r.z), h3 = __float2bfloat16(r.w);
        __nv_bfloat16 l0 = __float2bfloat16(r.x - __bfloat162float(h0));
        __nv_bfloat16 l1 = __float2bfloat16(r.y - __bfloat162float(h1));
        __nv_bfloat16 l2 = __float2bfloat16(r.z - __bfloat162float(h2));
        __nv_bfloat16 l3 = __float2bfloat16(r.w - __bfloat162float(h3));
        *(uint2*)&outh[idx] = make_uint2(pack_bf(h0, h1), pack_bf(h2, h3));
        *(uint2*)&outl[idx] = make_uint2(pack_bf(l0, l1), pack_bf(l2, l3));
    }
}

// ---------------- launcher ---------------------------------------------------
extern "C" void kernel_launch(void* const* d_in, const int* in_sizes, int n_in,
                              void* d_out, int out_size) {
    const float* x      = (const float*)d_in[0];
    const float* x_ctx  = (const float*)d_in[1];
    const float* dx_ctx = (const float*)d_in[2];
    const unsigned char* mask = (const unsigned char*)d_in[3];
    const float* qkv_w  = (const float*)d_in[4];
    const float* k_w    = (const float*)d_in[5];
    const float* v_w    = (const float*)d_in[6];
    const float* proj_w = (const float*)d_in[7];
    const float* proj_b = (const float*)d_in[8];
    float* out = (float*)d_out;

    float *p_qkv, *p_kctx, *p_vctx;
    cudaGetSymbolAddress((void**)&p_qkv,  g_qkv);
    cudaGetSymbolAddress((void**)&p_kctx, g_kctx);
    cudaGetSymbolAddress((void**)&p_vctx, g_vctx);

    __nv_bfloat16 *xh, *xl, *xch, *xcl, *dxh, *dxl, *qwh, *qwl,
                  *kwh, *kwl, *vwh, *vwl, *pwh, *pwl, *ah, *al;
    cudaGetSymbolAddress((void**)&xh,  g_xh);  cudaGetSymbolAddress((void**)&xl,  g_xl);
    cudaGetSymbolAddress((void**)&xch, g_xch); cudaGetSymbolAddress((void**)&xcl, g_xcl);
    cudaGetSymbolAddress((void**)&dxh, g_dxh); cudaGetSymbolAddress((void**)&dxl, g_dxl);
    cudaGetSymbolAddress((void**)&qwh, g_qwh); cudaGetSymbolAddress((void**)&qwl, g_qwl);
    cudaGetSymbolAddress((void**)&kwh, g_kwh); cudaGetSymbolAddress((void**)&kwl, g_kwl);
    cudaGetSymbolAddress((void**)&vwh, g_vwh); cudaGetSymbolAddress((void**)&vwl, g_vwl);
    cudaGetSymbolAddress((void**)&pwh, g_pwh); cudaGetSymbolAddress((void**)&pwl, g_pwl);
    cudaGetSymbolAddress((void**)&ah,  g_ah);  cudaGetSymbolAddress((void**)&al,  g_al);

    cudaFuncSetAttribute(gemm_tc, cudaFuncAttributeMaxDynamicSharedMemorySize, GEMM_SMEM);
    cudaFuncSetAttribute(attn_kernel, cudaFuncAttributeMaxDynamicSharedMemorySize,
                         (int)sizeof(AttnSmem));

    // 1: mask
    normalize_mask_kernel<<<1, 64>>>(mask);

    // 2: all splits in one launch
    SplitArgs sa;
    sa.src[0] = (const float4*)x;      sa.hi[0] = (uint2*)xh;  sa.lo[0] = (uint2*)xl;  sa.n4[0] = 3072 * 512 / 4;
    sa.src[1] = (const float4*)x_ctx;  sa.hi[1] = (uint2*)xch; sa.lo[1] = (uint2*)xcl; sa.n4[1] = 4096 * 512 / 4;
    sa.src[2] = (const float4*)dx_ctx; sa.hi[2] = (uint2*)dxh; sa.lo[2] = (uint2*)dxl; sa.n4[2] = 4096 * 512 / 4;
    sa.src[3] = (const float4*)qkv_w;  sa.hi[3] = (uint2*)qwh; sa.lo[3] = (uint2*)qwl; sa.n4[3] = 1536 * 512 / 4;
    sa.src[4] = (const float4*)k_w;    sa.hi[4] = (uint2*)kwh; sa.lo[4] = (uint2*)kwl; sa.n4[4] = 512 * 512 / 4;
    sa.src[5] = (const float4*)v_w;    sa.hi[5] = (uint2*)vwh; sa.lo[5] = (uint2*)vwl; sa.n4[5] = 512 * 512 / 4;
    sa.src[6] = (const float4*)proj_w; sa.hi[6] = (uint2*)pwh; sa.lo[6] = (uint2*)pwl; sa.n4[6] = 512 * 512 / 4;
    split_all<<<dim3(296, 7), 256>>>(sa);

    // 3: qkv = x @ qkv_w^T : [3072, 1536]
    gemm_tc<<<dim3(1536 / 64, 3072 / 128), 256, GEMM_SMEM>>>(
        xh, xl, qwh, qwl, nullptr, p_qkv, 3072, 1536, 512);
    // 4: k_ctx = dx_ctx @ k_w^T : [4096, 512]
    gemm_tc<<<dim3(512 / 64, 4096 / 128), 256, GEMM_SMEM>>>(
        dxh, dxl, kwh, kwl, nullptr, p_kctx, 4096, 512, 512);
    // 5: v_ctx = x_ctx @ v_w^T : [4096, 512]
    gemm_tc<<<dim3(512 / 64, 4096 / 128), 256, GEMM_SMEM>>>(
        xch, xcl, vwh, vwl, nullptr, p_vctx, 4096, 512, 512);

    // 6: fused masked flash attention (profiled launch) -> hi/lo bf16 splits
    attn_kernel<<<dim3(12, 8, 4), 256, sizeof(AttnSmem)>>>(
        p_qkv, p_kctx, p_vctx, ah, al);

    // 7: final projection + bias -> d_out
    gemm_tc<<<dim3(512 / 64, 3072 / 128), 256, GEMM_SMEM>>>(
        ah, al, pwh, pwl, proj_b, out, 3072, 512, 512);
}

// round 7
// speedup vs baseline: 2.3672x; 1.3271x over previous
#include <cuda_runtime.h>
#include <cuda_bf16.h>
#include <math.h>
#include <stdint.h>

// Problem constants: B=4, T=16, T0=12, L=64, C=512, H=8, hd=64, NUM_SEEDS=4

// ---------------- scratch (static device globals; no allocations) -----------
__device__ int g_maskn[64];                // normalized ctx_mask [b*16 + t]

// input splits (hi/lo bf16)
__device__ __align__(16) __nv_bfloat16 g_xh [3072 * 512], g_xl [3072 * 512];
__device__ __align__(16) __nv_bfloat16 g_xch[4096 * 512], g_xcl[4096 * 512];
__device__ __align__(16) __nv_bfloat16 g_dxh[4096 * 512], g_dxl[4096 * 512];
__device__ __align__(16) __nv_bfloat16 g_qwh[1536 * 512], g_qwl[1536 * 512];
__device__ __align__(16) __nv_bfloat16 g_kwh[ 512 * 512], g_kwl[ 512 * 512];
__device__ __align__(16) __nv_bfloat16 g_vwh[ 512 * 512], g_vwl[ 512 * 512];
__device__ __align__(16) __nv_bfloat16 g_pwh[ 512 * 512], g_pwl[ 512 * 512];
// intermediate GEMM outputs (hi/lo bf16)
__device__ __align__(16) __nv_bfloat16 g_qkvh[3072 * 1536], g_qkvl[3072 * 1536];
__device__ __align__(16) __nv_bfloat16 g_kcth[4096 * 512],  g_kctl[4096 * 512];
__device__ __align__(16) __nv_bfloat16 g_vcth[4096 * 512],  g_vctl[4096 * 512];
// attention output (hi/lo bf16)
__device__ __align__(16) __nv_bfloat16 g_ah [3072 * 512], g_al [3072 * 512];

// ---------------- helpers ----------------------------------------------------
__device__ __forceinline__ uint32_t s2u(const void* p) {
    uint32_t a;
    asm("{ .reg .u64 t; cvta.to.shared.u64 t, %1; cvt.u32.u64 %0, t; }"
        : "=r"(a) : "l"(p));
    return a;
}
__device__ __forceinline__ void cp16(uint32_t dst, const void* src) {
    asm volatile("cp.async.cg.shared.global [%0], [%1], 16;"
                 :: "r"(dst), "l"(src));
}
__device__ __forceinline__ void ldm_x4(uint32_t* r, uint32_t addr) {
    asm volatile("ldmatrix.sync.aligned.m8n8.x4.shared.b16 {%0,%1,%2,%3}, [%4];"
                 : "=r"(r[0]), "=r"(r[1]), "=r"(r[2]), "=r"(r[3]) : "r"(addr));
}
__device__ __forceinline__ void ldm_x4t(uint32_t* r, uint32_t addr) {
    asm volatile("ldmatrix.sync.aligned.m8n8.x4.trans.shared.b16 {%0,%1,%2,%3}, [%4];"
                 : "=r"(r[0]), "=r"(r[1]), "=r"(r[2]), "=r"(r[3]) : "r"(addr));
}
__device__ __forceinline__ void mma_bf16(float* c, const uint32_t* a, const uint32_t* b) {
    asm volatile(
        "mma.sync.aligned.m16n8k16.row.col.f32.bf16.bf16.f32 "
        "{%0,%1,%2,%3}, {%4,%5,%6,%7}, {%8,%9}, {%0,%1,%2,%3};"
        : "+f"(c[0]), "+f"(c[1]), "+f"(c[2]), "+f"(c[3])
        : "r"(a[0]), "r"(a[1]), "r"(a[2]), "r"(a[3]), "r"(b[0]), "r"(b[1]));
}
__device__ __forceinline__ uint32_t pack_bf(__nv_bfloat16 a, __nv_bfloat16 b) {
    return (uint32_t)__bfloat16_as_ushort(a) | ((uint32_t)__bfloat16_as_ushort(b) << 16);
}
__device__ __forceinline__ uint32_t pack_hi(float x, float y, float& rx, float& ry) {
    __nv_bfloat16 hx = __float2bfloat16(x), hy = __float2bfloat16(y);
    rx = x - __bfloat162float(hx);
    ry = y - __bfloat162float(hy);
    return pack_bf(hx, hy);
}

// ---------------- fused split: fp32 -> hi/lo bf16, all arrays ----------------
struct SplitArgs {
    const float4* src[7];
    uint2* hi[7];
    uint2* lo[7];
    int n4[7];
};
__global__ __launch_bounds__(256)
void split_all(SplitArgs a) {
    const int arr = blockIdx.y;
    const int n4 = a.n4[arr];
    const float4* __restrict__ s = a.src[arr];
    uint2* __restrict__ hp = a.hi[arr];
    uint2* __restrict__ lp = a.lo[arr];
    const int step = gridDim.x * 256;
    for (int i = blockIdx.x * 256 + threadIdx.x; i < n4; i += step) {
        float4 v = s[i];
        __nv_bfloat16 h0 = __float2bfloat16(v.x), h1 = __float2bfloat16(v.y);
        __nv_bfloat16 h2 = __float2bfloat16(v.z), h3 = __float2bfloat16(v.w);
        __nv_bfloat16 l0 = __float2bfloat16(v.x - __bfloat162float(h0));
        __nv_bfloat16 l1 = __float2bfloat16(v.y - __bfloat162float(h1));
        __nv_bfloat16 l2 = __float2bfloat16(v.z - __bfloat162float(h2));
        __nv_bfloat16 l3 = __float2bfloat16(v.w - __bfloat162float(h3));
        hp[i] = make_uint2(pack_bf(h0, h1), pack_bf(h2, h3));
        lp[i] = make_uint2(pack_bf(l0, l1), pack_bf(l2, l3));
    }
}

// ---------------- mask normalization (dtype-robust) --------------------------
__global__ void normalize_mask_kernel(const unsigned char* __restrict__ m8) {
    __shared__ int flag;
    int i = threadIdx.x;
    if (i == 0) flag = 0;
    __syncthreads();
    if ((i & 3) != 0 && m8[i] != 0) atomicOr(&flag, 1);
    __syncthreads();
    int v;
    if (flag) v = (m8[i] != 0) ? 1 : 0;
    else      v = (((const int*)m8)[i] != 0) ? 1 : 0;
    g_maskn[i] = v;
}

// ---------------- tensor-core split-bf16 GEMM: C = A @ W^T ------------------
// Output: fp32 C (+bias) if Ch==null, else hi/lo bf16 (Ch, Cl).
#define PITCHB 80
#define A_BYTES (128 * PITCHB)
#define B_BYTES (64 * PITCHB)
#define BUF_BYTES (2 * A_BYTES + 2 * B_BYTES)
#define GEMM_SMEM (2 * BUF_BYTES)

__global__ __launch_bounds__(256, 2)
void gemm_tc(const __nv_bfloat16* __restrict__ Ah, const __nv_bfloat16* __restrict__ Al,
             const __nv_bfloat16* __restrict__ Wh, const __nv_bfloat16* __restrict__ Wl,
             const float* __restrict__ bias, float* __restrict__ C,
             __nv_bfloat16* __restrict__ Ch, __nv_bfloat16* __restrict__ Cl,
             int M, int N, int K) {
    extern __shared__ char smem[];
    const uint32_t sb = s2u(smem);
    const int tid = threadIdx.x;
    const int wid = tid >> 5, lane = tid & 31;
    const int gid = lane >> 2, tig = lane & 3;
    const int bm = blockIdx.y * 128, bn = blockIdx.x * 64;
    const int wm = wid & 3, wn = wid >> 2;

    const int arow = tid >> 2;
    const int aseg = tid & 3;

    float acc[2][4][4];
#pragma unroll
    for (int mf = 0; mf < 2; mf++)
#pragma unroll
        for (int nf = 0; nf < 4; nf++)
#pragma unroll
            for (int r = 0; r < 4; r++) acc[mf][nf][r] = 0.f;

    const int nc = K >> 5;

    auto issue = [&](int c, int buf) {
        uint32_t base = sb + buf * BUF_BYTES;
        const int kofs = c * 32 + aseg * 8;
#pragma unroll
        for (int i = 0; i < 2; i++) {
            int row = arow + i * 64;
            uint32_t d = base + row * PITCHB + aseg * 16;
            cp16(d,            Ah + (size_t)(bm + row) * K + kofs);
            cp16(d + A_BYTES,  Al + (size_t)(bm + row) * K + kofs);
        }
        {
            int row = arow;
            uint32_t d = base + 2 * A_BYTES + row * PITCHB + aseg * 16;
            cp16(d,            Wh + (size_t)(bn + row) * K + kofs);
            cp16(d + B_BYTES,  Wl + (size_t)(bn + row) * K + kofs);
        }
        asm volatile("cp.async.commit_group;");
    };

    issue(0, 0);

    const uint32_t a_row16 = lane & 15;
    const uint32_t a_cofs  = (lane >> 4) * 16;
    const uint32_t b_nrow  = (lane & 7) + ((lane >> 4) & 1) * 8;
    const uint32_t b_kofs  = ((lane >> 3) & 1) * 16;

    for (int c = 0; c < nc; c++) {
        const int buf = c & 1;
        if (c + 1 < nc) {
            issue(c + 1, buf ^ 1);
            asm volatile("cp.async.wait_group 1;");
        } else {
            asm volatile("cp.async.wait_group 0;");
        }
        __syncthreads();

        const uint32_t abase = sb + buf * BUF_BYTES;
        const uint32_t bbase = abase + 2 * A_BYTES;

#pragma unroll
        for (int kf = 0; kf < 2; kf++) {
            uint32_t ah[2][4], al[2][4], bh[4][2], bl[4][2];
            const uint32_t kb = kf * 32;
#pragma unroll
            for (int mf = 0; mf < 2; mf++) {
                uint32_t ad = abase + (wm * 32 + mf * 16 + a_row16) * PITCHB
                            + a_cofs + kb;
                ldm_x4(ah[mf], ad);
                ldm_x4(al[mf], ad + A_BYTES);
            }
#pragma unroll
            for (int pr = 0; pr < 2; pr++) {
                uint32_t bd = bbase + (wn * 32 + pr * 16 + b_nrow) * PITCHB
                            + b_kofs + kb;
                uint32_t th[4], tl[4];
                ldm_x4(th, bd);
                ldm_x4(tl, bd + B_BYTES);
                bh[pr * 2 + 0][0] = th[0]; bh[pr * 2 + 0][1] = th[1];
                bh[pr * 2 + 1][0] = th[2]; bh[pr * 2 + 1][1] = th[3];
                bl[pr * 2 + 0][0] = tl[0]; bl[pr * 2 + 0][1] = tl[1];
                bl[pr * 2 + 1][0] = tl[2]; bl[pr * 2 + 1][1] = tl[3];
            }
#pragma unroll
            for (int mf = 0; mf < 2; mf++)
#pragma unroll
                for (int nf = 0; nf < 4; nf++) {
                    mma_bf16(acc[mf][nf], ah[mf], bh[nf]);
                    mma_bf16(acc[mf][nf], ah[mf], bl[nf]);
                    mma_bf16(acc[mf][nf], al[mf], bh[nf]);
                }
        }
        __syncthreads();
    }

    if (Ch) {
#pragma unroll
        for (int mf = 0; mf < 2; mf++) {
#pragma unroll
            for (int nf = 0; nf < 4; nf++) {
                int row = bm + wm * 32 + mf * 16 + gid;
                int col = bn + wn * 32 + nf * 8 + tig * 2;
                float r0, r1, r2, r3;
                uint32_t h0 = pack_hi(acc[mf][nf][0], acc[mf][nf][1], r0, r1);
                uint32_t h1 = pack_hi(acc[mf][nf][2], acc[mf][nf][3], r2, r3);
                *(uint32_t*)&Ch[(size_t)row * N + col] = h0;
                *(uint32_t*)&Ch[(size_t)(row + 8) * N + col] = h1;
                *(uint32_t*)&Cl[(size_t)row * N + col] =
                    pack_bf(__float2bfloat16(r0), __float2bfloat16(r1));
                *(uint32_t*)&Cl[(size_t)(row + 8) * N + col] =
                    pack_bf(__float2bfloat16(r2), __float2bfloat16(r3));
            }
        }
    } else {
#pragma unroll
        for (int mf = 0; mf < 2; mf++) {
#pragma unroll
            for (int nf = 0; nf < 4; nf++) {
                int row = bm + wm * 32 + mf * 16 + gid;
                int col = bn + wn * 32 + nf * 8 + tig * 2;
                float b0 = bias ? bias[col] : 0.f;
                float b1 = bias ? bias[col + 1] : 0.f;
                float2 v0 = make_float2(acc[mf][nf][0] + b0, acc[mf][nf][1] + b1);
                float2 v1 = make_float2(acc[mf][nf][2] + b0, acc[mf][nf][3] + b1);
                *(float2*)&C[(size_t)row * N + col] = v0;
                *(float2*)&C[(size_t)(row + 8) * N + col] = v1;
            }
        }
    }
}

// ---------------- tensor-core flash attention --------------------------------
// grid=(12,8,4), 128 threads (4 warps), warp owns 16 q rows.
// smem: Qh,Ql [64][72] bf16; double-buffered Kh,Kl,Vh,Vl [64][72].
#define APITCH 144                       // bytes per row (72 bf16)
#define TILE_B 9216                      // 64*144
#define QH_OFF 0
#define QL_OFF TILE_B
#define KV_OFF (2 * TILE_B)
#define KVBUF_B (4 * TILE_B)
#define ATTN_SMEM (2 * TILE_B + 2 * KVBUF_B)   // 92160

__global__ __launch_bounds__(128)
void attn_tc(const __nv_bfloat16* __restrict__ qkvh, const __nv_bfloat16* __restrict__ qkvl,
             const __nv_bfloat16* __restrict__ kcth, const __nv_bfloat16* __restrict__ kctl,
             const __nv_bfloat16* __restrict__ vcth, const __nv_bfloat16* __restrict__ vctl,
             __nv_bfloat16* __restrict__ outh, __nv_bfloat16* __restrict__ outl) {
    extern __shared__ char smem[];
    const uint32_t sb = s2u(smem);
    const int t0 = blockIdx.x, h = blockIdx.y, b = blockIdx.z;
    const int tid = threadIdx.x;
    const int w = tid >> 5, lane = tid & 31;
    const int gid = lane >> 2, tig = lane & 3;

    // chunk list (all threads compute identically)
    int ids[17], nv = 0;
    for (int t = 0; t < 16; t++)
        if (g_maskn[b * 16 + t] && t != t0 + 4) ids[nv++] = t;
    ids[nv++] = 16;   // self frame last

    const int seg = tid & 7;           // 16B segment within 128B row
    const int r0 = tid >> 3;           // 0..15

    // Q load (group 0, committed together with first KV chunk)
    {
        const size_t base = (size_t)(b * 768 + t0 * 64) * 1536 + h * 64 + seg * 8;
#pragma unroll
        for (int i = 0; i < 4; i++) {
            int row = r0 + i * 16;
            uint32_t d = sb + row * APITCH + seg * 16;
            cp16(d + QH_OFF, qkvh + base + (size_t)row * 1536);
            cp16(d + QL_OFF, qkvl + base + (size_t)row * 1536);
        }
    }

    auto issueKV = [&](int id, int buf) {
        const __nv_bfloat16 *ksh, *ksl, *vsh, *vsl;
        size_t kbase, vbase, rs;
        if (id < 16) {
            rs = 512;
            kbase = (size_t)(b * 1024 + id * 64) * 512 + h * 64 + seg * 8;
            vbase = kbase;
            ksh = kcth; ksl = kctl; vsh = vcth; vsl = vctl;
        } else {
            rs = 1536;
            size_t rb = (size_t)(b * 768 + t0 * 64) * 1536 + h * 64 + seg * 8;
            kbase = rb + 512; vbase = rb + 1024;
            ksh = qkvh; ksl = qkvl; vsh = qkvh; vsl = qkvl;
        }
        uint32_t base = sb + KV_OFF + buf * KVBUF_B;
#pragma unroll
        for (int i = 0; i < 4; i++) {
            int row = r0 + i * 16;
            uint32_t d = base + row * APITCH + seg * 16;
            cp16(d,              ksh + kbase + (size_t)row * rs);
            cp16(d + TILE_B,     ksl + kbase + (size_t)row * rs);
            cp16(d + 2 * TILE_B, vsh + vbase + (size_t)row * rs);
            cp16(d + 3 * TILE_B, vsl + vbase + (size_t)row * rs);
        }
        asm volatile("cp.async.commit_group;");
    };

    issueKV(ids[0], 0);

    const uint32_t a_row16 = lane & 15;
    const uint32_t a_cofs  = (lane >> 4) * 16;
    const uint32_t b_nrow  = (lane & 7) + ((lane >> 4) & 1) * 8;
    const uint32_t b_kofs  = ((lane >> 3) & 1) * 16;
    // V trans-ldmatrix lane addressing
    const uint32_t v_krow = lane & 15;
    const uint32_t v_dofs = (lane >> 4) * 16;

    uint32_t qh[4][4], ql[4][4];
    float of[8][4];
#pragma unroll
    for (int f = 0; f < 8; f++)
#pragma unroll
        for (int r = 0; r < 4; r++) of[f][r] = 0.f;
    float m1 = -INFINITY, m2 = -INFINITY, l1 = 0.f, l2 = 0.f;

    for (int i = 0; i < nv; i++) {
        if (i + 1 < nv) {
            issueKV(ids[i + 1], (i + 1) & 1);
            asm volatile("cp.async.wait_group 1;");
        } else {
            asm volatile("cp.async.wait_group 0;");
        }
        __syncthreads();

        if (i == 0) {   // Q fragments (smem Q never rewritten)
#pragma unroll
            for (int kf = 0; kf < 4; kf++) {
                uint32_t ad = sb + (w * 16 + a_row16) * APITCH + a_cofs + kf * 32;
                ldm_x4(qh[kf], ad + QH_OFF);
                ldm_x4(ql[kf], ad + QL_OFF);
            }
        }

        const uint32_t kvb = sb + KV_OFF + (i & 1) * KVBUF_B;

        // ---- S = Q @ K^T (3-term split) ----
        float sf[8][4];
#pragma unroll
        for (int f = 0; f < 8; f++)
#pragma unroll
            for (int r = 0; r < 4; r++) sf[f][r] = 0.f;

#pragma unroll
        for (int nfp = 0; nfp < 4; nfp++) {
#pragma unroll
            for (int kf = 0; kf < 4; kf++) {
                uint32_t th[4], tl[4];
                uint32_t kd = kvb + (nfp * 16 + b_nrow) * APITCH + b_kofs + kf * 32;
                ldm_x4(th, kd);
                ldm_x4(tl, kd + TILE_B);
                mma_bf16(sf[nfp * 2 + 0], qh[kf], &th[0]);
                mma_bf16(sf[nfp * 2 + 0], qh[kf], &tl[0]);
                mma_bf16(sf[nfp * 2 + 0], ql[kf], &th[0]);
                mma_bf16(sf[nfp * 2 + 1], qh[kf], &th[2]);
                mma_bf16(sf[nfp * 2 + 1], qh[kf], &tl[2]);
                mma_bf16(sf[nfp * 2 + 1], ql[kf], &th[2]);
            }
        }

        // ---- online softmax (scale 0.125) ----
        float cm1 = -INFINITY, cm2 = -INFINITY;
#pragma unroll
        for (int f = 0; f < 8; f++) {
            sf[f][0] *= 0.125f; sf[f][1] *= 0.125f;
            sf[f][2] *= 0.125f; sf[f][3] *= 0.125f;
            cm1 = fmaxf(cm1, fmaxf(sf[f][0], sf[f][1]));
            cm2 = fmaxf(cm2, fmaxf(sf[f][2], sf[f][3]));
        }
        cm1 = fmaxf(cm1, __shfl_xor_sync(0xffffffffu, cm1, 1));
        cm1 = fmaxf(cm1, __shfl_xor_sync(0xffffffffu, cm1, 2));
        cm2 = fmaxf(cm2, __shfl_xor_sync(0xffffffffu, cm2, 1));
        cm2 = fmaxf(cm2, __shfl_xor_sync(0xffffffffu, cm2, 2));
        float mn1 = fmaxf(m1, cm1), mn2 = fmaxf(m2, cm2);
        float f1 = __expf(m1 - mn1), f2 = __expf(m2 - mn2);  // -inf -> 0
        float rs1 = 0.f, rs2 = 0.f;
#pragma unroll
        for (int f = 0; f < 8; f++) {
            sf[f][0] = __expf(sf[f][0] - mn1);
            sf[f][1] = __expf(sf[f][1] - mn1);
            sf[f][2] = __expf(sf[f][2] - mn2);
            sf[f][3] = __expf(sf[f][3] - mn2);
            rs1 += sf[f][0] + sf[f][1];
            rs2 += sf[f][2] + sf[f][3];
        }
        rs1 += __shfl_xor_sync(0xffffffffu, rs1, 1);
        rs1 += __shfl_xor_sync(0xffffffffu, rs1, 2);
        rs2 += __shfl_xor_sync(0xffffffffu, rs2, 1);
        rs2 += __shfl_xor_sync(0xffffffffu, rs2, 2);
        l1 = l1 * f1 + rs1; l2 = l2 * f2 + rs2;
        m1 = mn1; m2 = mn2;
#pragma unroll
        for (int f = 0; f < 8; f++) {
            of[f][0] *= f1; of[f][1] *= f1;
            of[f][2] *= f2; of[f][3] *= f2;
        }

        // ---- P -> A fragments (2-term split) ----
        uint32_t ph[4][4], pl[4][4];
#pragma unroll
        for (int kf = 0; kf < 4; kf++) {
            float r0a, r1a, r2a, r3a;
            ph[kf][0] = pack_hi(sf[2 * kf][0], sf[2 * kf][1], r0a, r1a);
            pl[kf][0] = pack_bf(__float2bfloat16(r0a), __float2bfloat16(r1a));
            ph[kf][1] = pack_hi(sf[2 * kf][2], sf[2 * kf][3], r0a, r1a);
            pl[kf][1] = pack_bf(__float2bfloat16(r0a), __float2bfloat16(r1a));
            ph[kf][2] = pack_hi(sf[2 * kf + 1][0], sf[2 * kf + 1][1], r2a, r3a);
            pl[kf][2] = pack_bf(__float2bfloat16(r2a), __float2bfloat16(r3a));
            ph[kf][3] = pack_hi(sf[2 * kf + 1][2], sf[2 * kf + 1][3], r2a, r3a);
            pl[kf][3] = pack_bf(__float2bfloat16(r2a), __float2bfloat16(r3a));
        }

        // ---- O += P @ V (V via ldmatrix.trans) ----
        const uint32_t vb = kvb + 2 * TILE_B;
#pragma unroll
        for (int nfp = 0; nfp < 4; nfp++) {
#pragma unroll
            for (int kf = 0; kf < 4; kf++) {
                uint32_t vh_[4], vl_[4];
                uint32_t vd = vb + (kf * 16 + v_krow) * APITCH + nfp * 32 + v_dofs;
                ldm_x4t(vh_, vd);
                ldm_x4t(vl_, vd + TILE_B);
                mma_bf16(of[nfp * 2 + 0], ph[kf], &vh_[0]);
                mma_bf16(of[nfp * 2 + 0], ph[kf], &vl_[0]);
                mma_bf16(of[nfp * 2 + 0], pl[kf], &vh_[0]);
                mma_bf16(of[nfp * 2 + 1], ph[kf], &vh_[2]);
                mma_bf16(of[nfp * 2 + 1], ph[kf], &vl_[2]);
                mma_bf16(of[nfp * 2 + 1], pl[kf], &vh_[2]);
            }
        }
        __syncthreads();
    }

    // ---- finalize + write hi/lo bf16 ----
    const float inv1 = 1.0f / l1, inv2 = 1.0f / l2;
    const size_t row1 = (size_t)(b * 768 + t0 * 64 + w * 16 + gid);
    const size_t row2 = row1 + 8;
#pragma unroll
    for (int nf = 0; nf < 8; nf++) {
        int col = h * 64 + nf * 8 + tig * 2;
        float r0a, r1a;
        uint32_t h0 = pack_hi(of[nf][0] * inv1, of[nf][1] * inv1, r0a, r1a);
        *(uint32_t*)&outh[row1 * 512 + col] = h0;
        *(uint32_t*)&outl[row1 * 512 + col] =
            pack_bf(__float2bfloat16(r0a), __float2bfloat16(r1a));
        uint32_t h1 = pack_hi(of[nf][2] * inv2, of[nf][3] * inv2, r0a, r1a);
        *(uint32_t*)&outh[row2 * 512 + col] = h1;
        *(uint32_t*)&outl[row2 * 512 + col] =
            pack_bf(__float2bfloat16(r0a), __float2bfloat16(r1a));
    }
}

// ---------------- launcher ---------------------------------------------------
extern "C" void kernel_launch(void* const* d_in, const int* in_sizes, int n_in,
                              void* d_out, int out_size) {
    const float* x      = (const float*)d_in[0];
    const float* x_ctx  = (const float*)d_in[1];
    const float* dx_ctx = (const float*)d_in[2];
    const unsigned char* mask = (const unsigned char*)d_in[3];
    const float* qkv_w  = (const float*)d_in[4];
    const float* k_w    = (const float*)d_in[5];
    const float* v_w    = (const float*)d_in[6];
    const float* proj_w = (const float*)d_in[7];
    const float* proj_b = (const float*)d_in[8];
    float* out = (float*)d_out;

    __nv_bfloat16 *xh, *xl, *xch, *xcl, *dxh, *dxl, *qwh, *qwl,
                  *kwh, *kwl, *vwh, *vwl, *pwh, *pwl, *ah, *al,
                  *qkvh, *qkvl, *kcth, *kctl, *vcth, *vctl;
    cudaGetSymbolAddress((void**)&xh,  g_xh);  cudaGetSymbolAddress((void**)&xl,  g_xl);
    cudaGetSymbolAddress((void**)&xch, g_xch); cudaGetSymbolAddress((void**)&xcl, g_xcl);
    cudaGetSymbolAddress((void**)&dxh, g_dxh); cudaGetSymbolAddress((void**)&dxl, g_dxl);
    cudaGetSymbolAddress((void**)&qwh, g_qwh); cudaGetSymbolAddress((void**)&qwl, g_qwl);
    cudaGetSymbolAddress((void**)&kwh, g_kwh); cudaGetSymbolAddress((void**)&kwl, g_kwl);
    cudaGetSymbolAddress((void**)&vwh, g_vwh); cudaGetSymbolAddress((void**)&vwl, g_vwl);
    cudaGetSymbolAddress((void**)&pwh, g_pwh); cudaGetSymbolAddress((void**)&pwl, g_pwl);
    cudaGetSymbolAddress((void**)&ah,  g_ah);  cudaGetSymbolAddress((void**)&al,  g_al);
    cudaGetSymbolAddress((void**)&qkvh, g_qkvh); cudaGetSymbolAddress((void**)&qkvl, g_qkvl);
    cudaGetSymbolAddress((void**)&kcth, g_kcth); cudaGetSymbolAddress((void**)&kctl, g_kctl);
    cudaGetSymbolAddress((void**)&vcth, g_vcth); cudaGetSymbolAddress((void**)&vctl, g_vctl);

    cudaFuncSetAttribute(gemm_tc, cudaFuncAttributeMaxDynamicSharedMemorySize, GEMM_SMEM);
    cudaFuncSetAttribute(attn_tc, cudaFuncAttributeMaxDynamicSharedMemorySize, ATTN_SMEM);

    // 1: mask
    normalize_mask_kernel<<<1, 64>>>(mask);

    // 2: all input splits in one launch
    SplitArgs sa;
    sa.src[0] = (const float4*)x;      sa.hi[0] = (uint2*)xh;  sa.lo[0] = (uint2*)xl;  sa.n4[0] = 3072 * 512 / 4;
    sa.src[1] = (const float4*)x_ctx;  sa.hi[1] = (uint2*)xch; sa.lo[1] = (uint2*)xcl; sa.n4[1] = 4096 * 512 / 4;
    sa.src[2] = (const float4*)dx_ctx; sa.hi[2] = (uint2*)dxh; sa.lo[2] = (uint2*)dxl; sa.n4[2] = 4096 * 512 / 4;
    sa.src[3] = (const float4*)qkv_w;  sa.hi[3] = (uint2*)qwh; sa.lo[3] = (uint2*)qwl; sa.n4[3] = 1536 * 512 / 4;
    sa.src[4] = (const float4*)k_w;    sa.hi[4] = (uint2*)kwh; sa.lo[4] = (uint2*)kwl; sa.n4[4] = 512 * 512 / 4;
    sa.src[5] = (const float4*)v_w;    sa.hi[5] = (uint2*)vwh; sa.lo[5] = (uint2*)vwl; sa.n4[5] = 512 * 512 / 4;
    sa.src[6] = (const float4*)proj_w; sa.hi[6] = (uint2*)pwh; sa.lo[6] = (uint2*)pwl; sa.n4[6] = 512 * 512 / 4;
    split_all<<<dim3(296, 7), 256>>>(sa);

    // 3: qkv = x @ qkv_w^T -> hi/lo bf16
    gemm_tc<<<dim3(1536 / 64, 3072 / 128), 256, GEMM_SMEM>>>(
        xh, xl, qwh, qwl, nullptr, nullptr, qkvh, qkvl, 3072, 1536, 512);
    // 4: k_ctx = dx_ctx @ k_w^T -> hi/lo bf16
    gemm_tc<<<dim3(512 / 64, 4096 / 128), 256, GEMM_SMEM>>>(
        dxh, dxl, kwh, kwl, nullptr, nullptr, kcth, kctl, 4096, 512, 512);
    // 5: v_ctx = x_ctx @ v_w^T -> hi/lo bf16
    gemm_tc<<<dim3(512 / 64, 4096 / 128), 256, GEMM_SMEM>>>(
        xch, xcl, vwh, vwl, nullptr, nullptr, vcth, vctl, 4096, 512, 512);

    // 6: tensor-core flash attention -> hi/lo bf16 (profiled launch)
    attn_tc<<<dim3(12, 8, 4), 128, ATTN_SMEM>>>(
        qkvh, qkvl, kcth, kctl, vcth, vctl, ah, al);

    // 7: final projection + bias -> d_out (fp32)
    gemm_tc<<<dim3(512 / 64, 3072 / 128), 256, GEMM_SMEM>>>(
        ah, al, pwh, pwl, proj_b, out, nullptr, nullptr, 3072, 512, 512);
}